// round 2
// baseline (speedup 1.0000x reference)
#include <cuda_runtime.h>
#include <cuda_bf16.h>
#include <math.h>

// Problem dims (fixed by the reference)
#define NROWS 16384   // B*C = 1024*16
#define HDIM  1024    // D = H = EH = TH
#define NEXP  6
#define NTASK 3
#define TOPK  3

typedef unsigned long long ull;

// ---------------------------------------------------------------------------
// Scratch (device globals: allocation-free)
// ---------------------------------------------------------------------------
__device__ __align__(256) float g_h1[(long)NROWS * HDIM];            // 64 MB
__device__ __align__(256) float g_h [(long)NROWS * HDIM];            // 64 MB
__device__ __align__(256) float g_eh[(long)NEXP * NROWS * HDIM];     // 402 MB
__device__ __align__(256) float g_eo[(long)NEXP * NROWS * HDIM];     // 402 MB
__device__ __align__(256) float g_mo[(long)NTASK * NROWS * HDIM];    // 201 MB
__device__ __align__(256) float g_gates[(long)NTASK * NROWS * NEXP];

// ---------------------------------------------------------------------------
// Packed f32x2 FMA (Blackwell): d = a*b + d componentwise on two f32 lanes.
// ptxas will not auto-fuse this from C++; must be PTX.
// ---------------------------------------------------------------------------
__device__ __forceinline__ void ffma2(ull& d, ull a, ull b) {
    asm("fma.rn.f32x2 %0, %1, %2, %0;" : "+l"(d) : "l"(a), "l"(b));
}

union F2U { ull u; float2 f; };

// ---------------------------------------------------------------------------
// FFMA2 SGEMM: C[bz] = op(A[bz] @ B[bz] + bias[bz]);  A[M,K], B[K,N], rowmajor
// 128x128x16 tiles, 256 threads, 8x8 per-thread microtile as 8x4 f32x2 pairs.
// A tile is stored DUPLICATED in smem (As[k][2r]=As[k][2r+1]=A[r][k]) so that
// LDS.128 yields packed (a,a) operands with zero MOV overhead and pure
// broadcast addressing. Double-buffered over k.
// Requires M%128==0, N%128==0, K%16==0 (true for all calls here).
// ---------------------------------------------------------------------------
#define BM 128
#define BN 128
#define BK 16

template <bool RELU>
__global__ __launch_bounds__(256, 2)
void sgemm2_kernel(const float* __restrict__ A, const float* __restrict__ Bm,
                   const float* __restrict__ bias, float* __restrict__ C,
                   int K, int N, long sA, long sB, long sBias, long sC)
{
    const int bz = blockIdx.z;
    A    += (long)bz * sA;
    Bm   += (long)bz * sB;
    bias += (long)bz * sBias;
    C    += (long)bz * sC;

    __shared__ float As[2][BK][2 * BM];   // 32 KB (duplicated A)
    __shared__ float Bs[2][BK][BN];       // 16 KB

    const int tid = threadIdx.x;          // 0..255
    const int tx  = tid & 15;             // col group (8 cols)
    const int ty  = tid >> 4;             // row group (8 rows)

    const int row0 = blockIdx.y * BM;
    const int col0 = blockIdx.x * BN;

    // A loader: 2 float4 per thread; f = tid + 256*i -> row = f/4, k = (f%4)*4
    const int a_row = tid >> 2;           // 0..63 (i=1 adds 64)
    const int a_k   = (tid & 3) * 4;
    // B loader: 2 float4 per thread; f = tid + 256*i -> k = f/32, col=(f%32)*4
    const int b_k   = tid >> 5;           // 0..7 (i=1 adds 8)
    const int b_col = (tid & 31) * 4;

    const float* Ap0 = &A[(long)(row0 + a_row)      * K + a_k];
    const float* Ap1 = &A[(long)(row0 + a_row + 64) * K + a_k];
    const float* Bp0 = &Bm[(long)(b_k)     * N + col0 + b_col];
    const float* Bp1 = &Bm[(long)(b_k + 8) * N + col0 + b_col];

    ull acc[8][4];
#pragma unroll
    for (int i = 0; i < 8; i++)
#pragma unroll
        for (int j = 0; j < 4; j++) acc[i][j] = 0ull;

    // ---- preload tile 0 ----
    float4 a0 = *reinterpret_cast<const float4*>(Ap0);
    float4 a1 = *reinterpret_cast<const float4*>(Ap1);
    float4 b0 = *reinterpret_cast<const float4*>(Bp0);
    float4 b1 = *reinterpret_cast<const float4*>(Bp1);

#define STORE_TILE(buf)                                                        \
    do {                                                                       \
        *reinterpret_cast<float2*>(&As[buf][a_k + 0][2 * a_row])        = make_float2(a0.x, a0.x); \
        *reinterpret_cast<float2*>(&As[buf][a_k + 1][2 * a_row])        = make_float2(a0.y, a0.y); \
        *reinterpret_cast<float2*>(&As[buf][a_k + 2][2 * a_row])        = make_float2(a0.z, a0.z); \
        *reinterpret_cast<float2*>(&As[buf][a_k + 3][2 * a_row])        = make_float2(a0.w, a0.w); \
        *reinterpret_cast<float2*>(&As[buf][a_k + 0][2 * (a_row + 64)]) = make_float2(a1.x, a1.x); \
        *reinterpret_cast<float2*>(&As[buf][a_k + 1][2 * (a_row + 64)]) = make_float2(a1.y, a1.y); \
        *reinterpret_cast<float2*>(&As[buf][a_k + 2][2 * (a_row + 64)]) = make_float2(a1.z, a1.z); \
        *reinterpret_cast<float2*>(&As[buf][a_k + 3][2 * (a_row + 64)]) = make_float2(a1.w, a1.w); \
        *reinterpret_cast<float4*>(&Bs[buf][b_k][b_col])     = b0;             \
        *reinterpret_cast<float4*>(&Bs[buf][b_k + 8][b_col]) = b1;             \
    } while (0)

#define COMPUTE(buf)                                                           \
    do {                                                                       \
        _Pragma("unroll")                                                      \
        for (int kk = 0; kk < BK; kk++) {                                      \
            ull ap[8], bp[4];                                                  \
            const ulonglong2* pa =                                             \
                reinterpret_cast<const ulonglong2*>(&As[buf][kk][ty * 16]);    \
            ulonglong2 t0 = pa[0], t1 = pa[1], t2 = pa[2], t3 = pa[3];         \
            ap[0] = t0.x; ap[1] = t0.y; ap[2] = t1.x; ap[3] = t1.y;            \
            ap[4] = t2.x; ap[5] = t2.y; ap[6] = t3.x; ap[7] = t3.y;            \
            const ulonglong2* pb =                                             \
                reinterpret_cast<const ulonglong2*>(&Bs[buf][kk][tx * 8]);     \
            ulonglong2 u0 = pb[0], u1 = pb[1];                                 \
            bp[0] = u0.x; bp[1] = u0.y; bp[2] = u1.x; bp[3] = u1.y;            \
            _Pragma("unroll")                                                  \
            for (int i = 0; i < 8; i++)                                        \
                _Pragma("unroll")                                              \
                for (int j = 0; j < 4; j++)                                    \
                    ffma2(acc[i][j], ap[i], bp[j]);                            \
        }                                                                      \
    } while (0)

    STORE_TILE(0);
    __syncthreads();

    int buf = 0;
    for (int k0 = BK; k0 < K; k0 += BK) {
        // prefetch next tile (global) — overlaps with compute below
        a0 = *reinterpret_cast<const float4*>(Ap0 + k0);
        a1 = *reinterpret_cast<const float4*>(Ap1 + k0);
        b0 = *reinterpret_cast<const float4*>(Bp0 + (long)k0 * N);
        b1 = *reinterpret_cast<const float4*>(Bp1 + (long)k0 * N);

        COMPUTE(buf);

        buf ^= 1;
        STORE_TILE(buf);
        __syncthreads();
    }
    COMPUTE(buf);

    // Epilogue: bias (+ relu), vectorized store
#pragma unroll
    for (int i = 0; i < 8; i++) {
        const long r = row0 + ty * 8 + i;
        const int  c = col0 + tx * 8;
        F2U v0, v1, v2, v3;
        v0.u = acc[i][0]; v1.u = acc[i][1]; v2.u = acc[i][2]; v3.u = acc[i][3];
        float4 o0 = make_float4(v0.f.x + bias[c+0], v0.f.y + bias[c+1],
                                v1.f.x + bias[c+2], v1.f.y + bias[c+3]);
        float4 o1 = make_float4(v2.f.x + bias[c+4], v2.f.y + bias[c+5],
                                v3.f.x + bias[c+6], v3.f.y + bias[c+7]);
        if (RELU) {
            o0.x = fmaxf(o0.x, 0.f); o0.y = fmaxf(o0.y, 0.f);
            o0.z = fmaxf(o0.z, 0.f); o0.w = fmaxf(o0.w, 0.f);
            o1.x = fmaxf(o1.x, 0.f); o1.y = fmaxf(o1.y, 0.f);
            o1.z = fmaxf(o1.z, 0.f); o1.w = fmaxf(o1.w, 0.f);
        }
        *reinterpret_cast<float4*>(&C[r * N + c])     = o0;
        *reinterpret_cast<float4*>(&C[r * N + c + 4]) = o1;
    }
}

// ---------------------------------------------------------------------------
// Tower GEMM with fused final reduction (same FFMA2 mainloop):
//   th = relu(mo[t] @ tw1[t] + tb1[t]);  out[t,n] += th[n,:] . tw2[t,:]
// Epilogue reduces the 128-col tile and atomicAdds per (t,row).
// out must be pre-initialized to tb2[t].
// ---------------------------------------------------------------------------
__global__ __launch_bounds__(256, 2)
void tower2_kernel(const float* __restrict__ A, const float* __restrict__ Bm,
                   const float* __restrict__ bias, const float* __restrict__ w2,
                   float* __restrict__ out,
                   int M, int K, int N, long sA, long sB, long sBias, long sW2)
{
    const int bz = blockIdx.z;   // task
    A    += (long)bz * sA;
    Bm   += (long)bz * sB;
    bias += (long)bz * sBias;
    w2   += (long)bz * sW2;
    float* out_t = out + (long)bz * M;

    __shared__ float As[2][BK][2 * BM];
    __shared__ float Bs[2][BK][BN];

    const int tid = threadIdx.x;
    const int tx  = tid & 15;
    const int ty  = tid >> 4;

    const int row0 = blockIdx.y * BM;
    const int col0 = blockIdx.x * BN;

    const int a_row = tid >> 2;
    const int a_k   = (tid & 3) * 4;
    const int b_k   = tid >> 5;
    const int b_col = (tid & 31) * 4;

    const float* Ap0 = &A[(long)(row0 + a_row)      * K + a_k];
    const float* Ap1 = &A[(long)(row0 + a_row + 64) * K + a_k];
    const float* Bp0 = &Bm[(long)(b_k)     * N + col0 + b_col];
    const float* Bp1 = &Bm[(long)(b_k + 8) * N + col0 + b_col];

    ull acc[8][4];
#pragma unroll
    for (int i = 0; i < 8; i++)
#pragma unroll
        for (int j = 0; j < 4; j++) acc[i][j] = 0ull;

    float4 a0 = *reinterpret_cast<const float4*>(Ap0);
    float4 a1 = *reinterpret_cast<const float4*>(Ap1);
    float4 b0 = *reinterpret_cast<const float4*>(Bp0);
    float4 b1 = *reinterpret_cast<const float4*>(Bp1);

    STORE_TILE(0);
    __syncthreads();

    int buf = 0;
    for (int k0 = BK; k0 < K; k0 += BK) {
        a0 = *reinterpret_cast<const float4*>(Ap0 + k0);
        a1 = *reinterpret_cast<const float4*>(Ap1 + k0);
        b0 = *reinterpret_cast<const float4*>(Bp0 + (long)k0 * N);
        b1 = *reinterpret_cast<const float4*>(Bp1 + (long)k0 * N);

        COMPUTE(buf);

        buf ^= 1;
        STORE_TILE(buf);
        __syncthreads();
    }
    COMPUTE(buf);

    // Epilogue: relu(acc+bias) * w2, reduce over this block's 128 cols
    const int c0 = col0 + tx * 8;
    float w2v[8], bv[8];
#pragma unroll
    for (int j = 0; j < 8; j++) { w2v[j] = w2[c0 + j]; bv[j] = bias[c0 + j]; }

    float partial[8];
#pragma unroll
    for (int i = 0; i < 8; i++) {
        F2U v[4];
#pragma unroll
        for (int j = 0; j < 4; j++) v[j].u = acc[i][j];
        float p = 0.f;
#pragma unroll
        for (int j = 0; j < 4; j++) {
            p = fmaf(fmaxf(v[j].f.x + bv[2*j],   0.f), w2v[2*j],   p);
            p = fmaf(fmaxf(v[j].f.y + bv[2*j+1], 0.f), w2v[2*j+1], p);
        }
        partial[i] = p;
    }
    // 16-lane (tx) reduction within the warp
#pragma unroll
    for (int off = 8; off > 0; off >>= 1)
#pragma unroll
        for (int i = 0; i < 8; i++)
            partial[i] += __shfl_down_sync(0xffffffffu, partial[i], off);

    if (tx == 0) {
#pragma unroll
        for (int i = 0; i < 8; i++)
            atomicAdd(&out_t[row0 + ty * 8 + i], partial[i]);
    }
}

// ---------------------------------------------------------------------------
// Gating: one warp per (t, n). logits[e] = h[n,:] . w_gate[t,:,e];
// top-3 -> softmax -> dense gates[t,n,0..5].
// ---------------------------------------------------------------------------
__global__ __launch_bounds__(256)
void gate_kernel(const float* __restrict__ h, const float* __restrict__ wg,
                 float* __restrict__ gates)
{
    const int warp = (blockIdx.x * blockDim.x + threadIdx.x) >> 5;
    const int lane = threadIdx.x & 31;
    if (warp >= NTASK * NROWS) return;
    const int t = warp / NROWS;
    const int n = warp - t * NROWS;

    float acc[NEXP];
#pragma unroll
    for (int e = 0; e < NEXP; e++) acc[e] = 0.f;

    const float* hrow = h + (long)n * HDIM;
    const float* wt   = wg + (long)t * HDIM * NEXP;
    for (int hh = lane; hh < HDIM; hh += 32) {
        const float hv = hrow[hh];
        const float* wr = wt + (long)hh * NEXP;
#pragma unroll
        for (int e = 0; e < NEXP; e++)
            acc[e] = fmaf(hv, wr[e], acc[e]);
    }
#pragma unroll
    for (int off = 16; off > 0; off >>= 1)
#pragma unroll
        for (int e = 0; e < NEXP; e++)
            acc[e] += __shfl_xor_sync(0xffffffffu, acc[e], off);

    if (lane == 0) {
        float v[NEXP];
#pragma unroll
        for (int e = 0; e < NEXP; e++) v[e] = acc[e];
        int   ti[TOPK];
        float tv[TOPK];
#pragma unroll
        for (int s = 0; s < TOPK; s++) {
            int bi = 0; float bv = v[0];
#pragma unroll
            for (int e = 1; e < NEXP; e++)
                if (v[e] > bv) { bv = v[e]; bi = e; }
            ti[s] = bi; tv[s] = bv; v[bi] = -INFINITY;
        }
        const float m = tv[0];
        float w[TOPK], s = 0.f;
#pragma unroll
        for (int k = 0; k < TOPK; k++) { w[k] = expf(tv[k] - m); s += w[k]; }
        const float inv = 1.f / s;
        float gv[NEXP];
#pragma unroll
        for (int e = 0; e < NEXP; e++) gv[e] = 0.f;
#pragma unroll
        for (int k = 0; k < TOPK; k++) gv[ti[k]] = w[k] * inv;
        float* gp = gates + ((long)t * NROWS + n) * NEXP;
#pragma unroll
        for (int e = 0; e < NEXP; e++) gp[e] = gv[e];
    }
}

// ---------------------------------------------------------------------------
// Gate combine: mo[t,n,h] = sum_e gates[t,n,e] * eo[e,n,h]
// ---------------------------------------------------------------------------
__global__ __launch_bounds__(256)
void combine_kernel(const float* __restrict__ eo, const float* __restrict__ gates,
                    float* __restrict__ mo)
{
    const long nh  = (long)NROWS * HDIM;
    const long idx = (long)blockIdx.x * blockDim.x + threadIdx.x;
    if (idx >= nh) return;
    const int n = (int)(idx >> 10);   // HDIM = 1024

    float v[NEXP];
#pragma unroll
    for (int e = 0; e < NEXP; e++) v[e] = eo[(long)e * nh + idx];

#pragma unroll
    for (int t = 0; t < NTASK; t++) {
        const float* gp = gates + ((long)t * NROWS + n) * NEXP;
        float r = 0.f;
#pragma unroll
        for (int e = 0; e < NEXP; e++) r = fmaf(gp[e], v[e], r);
        mo[(long)t * nh + idx] = r;
    }
}

// ---------------------------------------------------------------------------
__global__ void init_out_kernel(float* __restrict__ out, const float* __restrict__ tb2)
{
    const int i = blockIdx.x * blockDim.x + threadIdx.x;
    if (i < NTASK * NROWS) out[i] = tb2[i / NROWS];
}

// ---------------------------------------------------------------------------
extern "C" void kernel_launch(void* const* d_in, const int* in_sizes, int n_in,
                              void* d_out, int out_size)
{
    const float* cls   = (const float*)d_in[0];
    const float* fc1w  = (const float*)d_in[1];
    const float* fc1b  = (const float*)d_in[2];
    const float* fc2w  = (const float*)d_in[3];
    const float* fc2b  = (const float*)d_in[4];
    const float* wgate = (const float*)d_in[5];
    const float* ew1   = (const float*)d_in[6];
    const float* eb1   = (const float*)d_in[7];
    const float* ew2   = (const float*)d_in[8];
    const float* eb2   = (const float*)d_in[9];
    const float* tw1   = (const float*)d_in[10];
    const float* tb1   = (const float*)d_in[11];
    const float* tw2   = (const float*)d_in[12];
    const float* tb2   = (const float*)d_in[13];
    float* out = (float*)d_out;

    float *h1, *h, *eh, *eo, *mo, *gates;
    cudaGetSymbolAddress((void**)&h1,    g_h1);
    cudaGetSymbolAddress((void**)&h,     g_h);
    cudaGetSymbolAddress((void**)&eh,    g_eh);
    cudaGetSymbolAddress((void**)&eo,    g_eo);
    cudaGetSymbolAddress((void**)&mo,    g_mo);
    cudaGetSymbolAddress((void**)&gates, g_gates);

    const dim3 blk(256);
    const long HH = (long)HDIM * HDIM;
    const long NH = (long)NROWS * HDIM;
    const dim3 g1(8, 128, 1), gE(8, 128, NEXP), gT(8, 128, NTASK);

    // shared bottom
    sgemm2_kernel<true ><<<g1, blk>>>(cls, fc1w, fc1b, h1, HDIM, HDIM, 0, 0, 0, 0);
    sgemm2_kernel<false><<<g1, blk>>>(h1, fc2w, fc2b, h,  HDIM, HDIM, 0, 0, 0, 0);

    // gating
    gate_kernel<<<(NTASK * NROWS) / 8, blk>>>(h, wgate, gates);

    // experts
    sgemm2_kernel<true ><<<gE, blk>>>(h,  ew1, eb1, eh, HDIM, HDIM, 0,  HH, HDIM, NH);
    sgemm2_kernel<false><<<gE, blk>>>(eh, ew2, eb2, eo, HDIM, HDIM, NH, HH, HDIM, NH);

    // gate combine
    combine_kernel<<<(unsigned)(NH / 256), blk>>>(eo, gates, mo);

    // towers (fused final dot via atomics)
    init_out_kernel<<<(NTASK * NROWS + 255) / 256, blk>>>(out, tb2);
    tower2_kernel<<<gT, blk>>>(mo, tw1, tb1, tw2, out,
                               NROWS, HDIM, HDIM, NH, HH, HDIM, HDIM);
}

// round 5
// speedup vs baseline: 2.6758x; 2.6758x over previous
#include <cuda_runtime.h>
#include <cuda_bf16.h>
#include <math.h>
#include <stdint.h>

#define NROWS 16384
#define HDIM  1024
#define NEXP  6
#define NTASK 3
#define TOPK  3

typedef __nv_bfloat16 bf16;
#define NH_ ((long)NROWS * HDIM)          // 16777216
#define HH_ ((long)HDIM * HDIM)           // 1048576

// =============================== Scratch ===================================
__device__ __align__(256) bf16  g_cls[3 * NH_];            // 96 MB (3-way split)
__device__ __align__(256) bf16  g_h1 [3 * NH_];            // 96 MB
__device__ __align__(256) bf16  g_h  [2 * NH_];            // 64 MB
__device__ __align__(256) float g_hf [NH_];                // 64 MB
__device__ __align__(256) bf16  g_eh [2 * NEXP * NH_];     // 384 MB
__device__ __align__(256) float g_eo [NEXP * NH_];         // 384 MB
__device__ __align__(256) bf16  g_mo [2 * NTASK * NH_];    // 192 MB
__device__ __align__(256) float g_gates[(long)NTASK * NROWS * NEXP];
__device__ __align__(256) bf16  g_w3 [6 * HH_];            // fc1(3) fc2(3)
__device__ __align__(256) bf16  g_w2 [30 * HH_];           // ew1(6),ew2(6),tw1(3) x2 comps

// =============================== PTX helpers ===============================
__device__ __forceinline__ uint32_t smem_u32(const void* p) {
    uint32_t a;
    asm("{ .reg .u64 t; cvta.to.shared.u64 t, %1; cvt.u32.u64 %0, t; }" : "=r"(a) : "l"(p));
    return a;
}
__device__ __forceinline__ void cp16(uint32_t s, const void* g) {
    asm volatile("cp.async.cg.shared.global [%0], [%1], 16;" :: "r"(s), "l"(g) : "memory");
}
#define CP_COMMIT() asm volatile("cp.async.commit_group;" ::: "memory")
#define CP_WAIT1()  asm volatile("cp.async.wait_group 1;" ::: "memory")
#define CP_WAIT0()  asm volatile("cp.async.wait_group 0;" ::: "memory")

__device__ __forceinline__ void ldsm4(uint32_t (&r)[4], uint32_t addr) {
    asm volatile("ldmatrix.sync.aligned.m8n8.x4.shared.b16 {%0,%1,%2,%3}, [%4];"
                 : "=r"(r[0]), "=r"(r[1]), "=r"(r[2]), "=r"(r[3]) : "r"(addr));
}
__device__ __forceinline__ void mma_bf16(float (&d)[4], const uint32_t (&a)[4],
                                         uint32_t b0, uint32_t b1) {
    asm volatile(
        "mma.sync.aligned.m16n8k16.row.col.f32.bf16.bf16.f32 "
        "{%0,%1,%2,%3}, {%4,%5,%6,%7}, {%8,%9}, {%0,%1,%2,%3};"
        : "+f"(d[0]), "+f"(d[1]), "+f"(d[2]), "+f"(d[3])
        : "r"(a[0]), "r"(a[1]), "r"(a[2]), "r"(a[3]), "r"(b0), "r"(b1));
}

// ============================ split-bf16 GEMM ==============================
// C = op( (sum_i A_i) @ (sum_j B_j)^T + bias ), keeping mma terms i+j < NSPL.
// A[M,K] row-major comps; B[N,K] row-major comps (pre-transposed weights).
// CTA tile 128x128, K-chunk 32, 8 warps (4m x 2n), warp tile 32x64.
#define BM 128
#define BN 128
#define BK 32
#define NKCH (HDIM / BK)          // 32
#define MB_  10240                // one 128x32 bf16 matrix, 80B row stride
#define ROWB 80

template <int NSPL, bool RELU, bool WF32, int WSPL, bool TOWER>
__global__ void __launch_bounds__(256, NSPL == 2 ? 2 : 1)
mma_gemm(const bf16* __restrict__ A0, const bf16* __restrict__ A1, const bf16* __restrict__ A2,
         const bf16* __restrict__ B0, const bf16* __restrict__ B1, const bf16* __restrict__ B2,
         const float* __restrict__ bias,
         float* __restrict__ Cf, bf16* __restrict__ C0, bf16* __restrict__ C1,
         bf16* __restrict__ C2,
         const float* __restrict__ w2, float* __restrict__ outT,
         long sA, long sB, long sBias, long sC, long sW2)
{
    extern __shared__ char smem[];
    const uint32_t smbase = smem_u32(smem);
    const int tid = threadIdx.x, wid = tid >> 5, lane = tid & 31;
    const int z = blockIdx.z;
    const long row0 = (long)blockIdx.y * BM;
    const int  n0   = blockIdx.x * BN;

    const bf16* Ag[3];
    const bf16* Bg[3];
    Ag[0] = A0 + z * sA + row0 * HDIM;
    Ag[1] = A1 + z * sA + row0 * HDIM;
    Ag[2] = (NSPL > 2) ? (A2 + z * sA + row0 * HDIM) : nullptr;
    Bg[0] = B0 + z * sB + (long)n0 * HDIM;
    Bg[1] = B1 + z * sB + (long)n0 * HDIM;
    Bg[2] = (NSPL > 2) ? (B2 + z * sB + (long)n0 * HDIM) : nullptr;

    const uint32_t STAGE = 2 * NSPL * MB_;

    // stage loader: 512 (row,chunk) slots, 2*NSPL matrices
    auto ldstage = [&](int buf, int kc0) {
        const uint32_t sb = smbase + buf * STAGE;
#pragma unroll
        for (int i = 0; i < 2; i++) {
            const int v = tid + 256 * i;
            const int r = v >> 2, ch = v & 3;
            const long g = (long)r * HDIM + kc0 + ch * 8;
            const uint32_t so = (uint32_t)(r * ROWB + ch * 16);
#pragma unroll
            for (int c = 0; c < NSPL; c++) {
                cp16(sb + c * MB_ + so, Ag[c] + g);
                cp16(sb + (NSPL + c) * MB_ + so, Bg[c] + g);
            }
        }
    };

    float acc[2][8][4];
#pragma unroll
    for (int mt = 0; mt < 2; mt++)
#pragma unroll
        for (int nt = 0; nt < 8; nt++)
#pragma unroll
            for (int q = 0; q < 4; q++) acc[mt][nt][q] = 0.f;

    const int wm = (wid >> 1) * 32;      // warp m offset in tile
    const int wn = (wid & 1) * 64;       // warp n offset
    const int grp = lane >> 3, lr = lane & 7;
    const int arow = lr + ((grp & 1) << 3);           // A fragment rows
    const int akb  = (grp >> 1) << 4;
    const int brow = lr + ((grp >> 1) << 3);          // B fragment rows
    const int bkb  = (grp & 1) << 4;

    ldstage(0, 0);
    CP_COMMIT();

    for (int c = 0; c < NKCH; c++) {
        if (c + 1 < NKCH) { ldstage((c + 1) & 1, (c + 1) * BK); CP_COMMIT(); CP_WAIT1(); }
        else              { CP_WAIT0(); }
        __syncthreads();

        const uint32_t sb = smbase + (c & 1) * STAGE;
#pragma unroll
        for (int ks = 0; ks < 2; ks++) {
            uint32_t af[NSPL][2][4];
#pragma unroll
            for (int sc = 0; sc < NSPL; sc++)
#pragma unroll
                for (int mt = 0; mt < 2; mt++)
                    ldsm4(af[sc][mt],
                          sb + sc * MB_ + (wm + mt * 16 + arow) * ROWB + ks * 32 + akb);
#pragma unroll
            for (int np = 0; np < 4; np++) {
                uint32_t bfr[NSPL][4];
#pragma unroll
                for (int sc = 0; sc < NSPL; sc++)
                    ldsm4(bfr[sc],
                          sb + (NSPL + sc) * MB_ + (wn + np * 16 + brow) * ROWB + ks * 32 + bkb);
#pragma unroll
                for (int mt = 0; mt < 2; mt++) {
#pragma unroll
                    for (int i = 0; i < NSPL; i++)
#pragma unroll
                        for (int j = 0; j < NSPL; j++) {
                            if (i + j < NSPL) {
                                mma_bf16(acc[mt][2 * np],     af[i][mt], bfr[j][0], bfr[j][1]);
                                mma_bf16(acc[mt][2 * np + 1], af[i][mt], bfr[j][2], bfr[j][3]);
                            }
                        }
                }
            }
        }
        __syncthreads();
    }

    // ------------------------------ epilogue ------------------------------
    const float* biasz = bias + z * sBias;
    const float* w2z   = TOWER ? (w2 + z * sW2) : nullptr;

#pragma unroll
    for (int mt = 0; mt < 2; mt++) {
#pragma unroll
        for (int half = 0; half < 2; half++) {
            const long gr = row0 + wm + mt * 16 + (lane >> 2) + half * 8;
            float p = 0.f;
#pragma unroll
            for (int nt = 0; nt < 8; nt++) {
                const int cc = n0 + wn + nt * 8 + (lane & 3) * 2;
                float v0 = acc[mt][nt][half * 2 + 0] + biasz[cc];
                float v1 = acc[mt][nt][half * 2 + 1] + biasz[cc + 1];
                if (RELU || TOWER) { v0 = fmaxf(v0, 0.f); v1 = fmaxf(v1, 0.f); }
                if (TOWER) {
                    p = fmaf(v0, w2z[cc], p);
                    p = fmaf(v1, w2z[cc + 1], p);
                } else {
                    const long off = z * sC + gr * HDIM + cc;
                    if (WF32)
                        *reinterpret_cast<float2*>(&Cf[off]) = make_float2(v0, v1);
                    if (WSPL >= 2) {
                        bf16 h0 = __float2bfloat16(v0), h1 = __float2bfloat16(v1);
                        float r0 = v0 - __bfloat162float(h0);
                        float r1 = v1 - __bfloat162float(h1);
                        bf16 m0 = __float2bfloat16(r0), m1 = __float2bfloat16(r1);
                        *reinterpret_cast<uint32_t*>(&C0[off]) =
                            (uint32_t)__bfloat16_as_ushort(h0) |
                            ((uint32_t)__bfloat16_as_ushort(h1) << 16);
                        *reinterpret_cast<uint32_t*>(&C1[off]) =
                            (uint32_t)__bfloat16_as_ushort(m0) |
                            ((uint32_t)__bfloat16_as_ushort(m1) << 16);
                        if (WSPL == 3) {
                            bf16 l0 = __float2bfloat16(r0 - __bfloat162float(m0));
                            bf16 l1 = __float2bfloat16(r1 - __bfloat162float(m1));
                            *reinterpret_cast<uint32_t*>(&C2[off]) =
                                (uint32_t)__bfloat16_as_ushort(l0) |
                                ((uint32_t)__bfloat16_as_ushort(l1) << 16);
                        }
                    }
                }
            }
            if (TOWER) {
                p += __shfl_down_sync(0xffffffffu, p, 2);
                p += __shfl_down_sync(0xffffffffu, p, 1);
                if ((lane & 3) == 0)
                    atomicAdd(&outT[(long)z * NROWS + gr], p);
            }
        }
    }
}

// ======================= conversion / small kernels ========================
__global__ __launch_bounds__(256)
void cvt3_kernel(const float* __restrict__ in, bf16* __restrict__ c0,
                 bf16* __restrict__ c1, bf16* __restrict__ c2, long n)
{
    const long i = (long)blockIdx.x * blockDim.x + threadIdx.x;
    if (i >= n) return;
    const float v = in[i];
    const bf16 h = __float2bfloat16(v);
    const float r = v - __bfloat162float(h);
    const bf16 m = __float2bfloat16(r);
    c0[i] = h;
    c1[i] = m;
    c2[i] = __float2bfloat16(r - __bfloat162float(m));
}

// W[z][k][n] -> T comps [z][n][k]
template <int NSPL>
__global__ __launch_bounds__(256)
void transpose_w(const float* __restrict__ W, bf16* __restrict__ T0,
                 bf16* __restrict__ T1, bf16* __restrict__ T2, long zstride)
{
    __shared__ float tile[32][33];
    const int z = blockIdx.z;
    const float* Wz = W + (long)z * HH_;
    const long ob = (long)z * zstride;
    const int k0 = blockIdx.y * 32, n0 = blockIdx.x * 32;
    for (int i = threadIdx.y; i < 32; i += 8)
        tile[i][threadIdx.x] = Wz[(long)(k0 + i) * HDIM + n0 + threadIdx.x];
    __syncthreads();
    for (int i = threadIdx.y; i < 32; i += 8) {
        const float v = tile[threadIdx.x][i];
        const bf16 h = __float2bfloat16(v);
        const float r = v - __bfloat162float(h);
        const bf16 m = __float2bfloat16(r);
        const long o = ob + (long)(n0 + i) * HDIM + k0 + threadIdx.x;
        T0[o] = h;
        T1[o + HH_] = m;   // comp1 at +HH_
        if (NSPL == 3)
            T2[o + 2 * HH_] = __float2bfloat16(r - __bfloat162float(m));
    }
}

__global__ __launch_bounds__(256)
void gate_kernel(const float* __restrict__ h, const float* __restrict__ wg,
                 float* __restrict__ gates)
{
    const int warp = (blockIdx.x * blockDim.x + threadIdx.x) >> 5;
    const int lane = threadIdx.x & 31;
    if (warp >= NTASK * NROWS) return;
    const int t = warp / NROWS;
    const int n = warp - t * NROWS;

    float acc[NEXP];
#pragma unroll
    for (int e = 0; e < NEXP; e++) acc[e] = 0.f;
    const float* hrow = h + (long)n * HDIM;
    const float* wt   = wg + (long)t * HDIM * NEXP;
    for (int hh = lane; hh < HDIM; hh += 32) {
        const float hv = hrow[hh];
        const float* wr = wt + (long)hh * NEXP;
#pragma unroll
        for (int e = 0; e < NEXP; e++) acc[e] = fmaf(hv, wr[e], acc[e]);
    }
#pragma unroll
    for (int off = 16; off > 0; off >>= 1)
#pragma unroll
        for (int e = 0; e < NEXP; e++)
            acc[e] += __shfl_xor_sync(0xffffffffu, acc[e], off);

    if (lane == 0) {
        float v[NEXP];
#pragma unroll
        for (int e = 0; e < NEXP; e++) v[e] = acc[e];
        int ti[TOPK]; float tv[TOPK];
#pragma unroll
        for (int s = 0; s < TOPK; s++) {
            int bi = 0; float bv = v[0];
#pragma unroll
            for (int e = 1; e < NEXP; e++) if (v[e] > bv) { bv = v[e]; bi = e; }
            ti[s] = bi; tv[s] = bv; v[bi] = -INFINITY;
        }
        const float m = tv[0];
        float w[TOPK], s = 0.f;
#pragma unroll
        for (int k = 0; k < TOPK; k++) { w[k] = expf(tv[k] - m); s += w[k]; }
        const float inv = 1.f / s;
        float gv[NEXP];
#pragma unroll
        for (int e = 0; e < NEXP; e++) gv[e] = 0.f;
#pragma unroll
        for (int k = 0; k < TOPK; k++) gv[ti[k]] = w[k] * inv;
        float* gp = gates + ((long)t * NROWS + n) * NEXP;
#pragma unroll
        for (int e = 0; e < NEXP; e++) gp[e] = gv[e];
    }
}

__global__ __launch_bounds__(256)
void combine_kernel(const float* __restrict__ eo, const float* __restrict__ gates,
                    bf16* __restrict__ m0, bf16* __restrict__ m1)
{
    const long idx = (long)blockIdx.x * blockDim.x + threadIdx.x;
    if (idx >= NH_) return;
    const int n = (int)(idx >> 10);

    float v[NEXP];
#pragma unroll
    for (int e = 0; e < NEXP; e++) v[e] = eo[(long)e * NH_ + idx];

#pragma unroll
    for (int t = 0; t < NTASK; t++) {
        const float* gp = gates + ((long)t * NROWS + n) * NEXP;
        float r = 0.f;
#pragma unroll
        for (int e = 0; e < NEXP; e++) r = fmaf(gp[e], v[e], r);
        const bf16 h = __float2bfloat16(r);
        m0[(long)t * NH_ + idx] = h;
        m1[(long)t * NH_ + idx] = __float2bfloat16(r - __bfloat162float(h));
    }
}

__global__ void init_out_kernel(float* __restrict__ out, const float* __restrict__ tb2)
{
    const int i = blockIdx.x * blockDim.x + threadIdx.x;
    if (i < NTASK * NROWS) out[i] = tb2[i / NROWS];
}

// ================================ launch ===================================
extern "C" void kernel_launch(void* const* d_in, const int* in_sizes, int n_in,
                              void* d_out, int out_size)
{
    const float* cls   = (const float*)d_in[0];
    const float* fc1w  = (const float*)d_in[1];
    const float* fc1b  = (const float*)d_in[2];
    const float* fc2w  = (const float*)d_in[3];
    const float* fc2b  = (const float*)d_in[4];
    const float* wgate = (const float*)d_in[5];
    const float* ew1   = (const float*)d_in[6];
    const float* eb1   = (const float*)d_in[7];
    const float* ew2   = (const float*)d_in[8];
    const float* eb2   = (const float*)d_in[9];
    const float* tw1   = (const float*)d_in[10];
    const float* tb1   = (const float*)d_in[11];
    const float* tw2   = (const float*)d_in[12];
    const float* tb2   = (const float*)d_in[13];
    float* out = (float*)d_out;

    bf16 *clsS, *h1S, *hS, *ehS, *moS, *w3, *w2p;
    float *hf, *eo, *gates;
    cudaGetSymbolAddress((void**)&clsS, g_cls);
    cudaGetSymbolAddress((void**)&h1S,  g_h1);
    cudaGetSymbolAddress((void**)&hS,   g_h);
    cudaGetSymbolAddress((void**)&hf,   g_hf);
    cudaGetSymbolAddress((void**)&ehS,  g_eh);
    cudaGetSymbolAddress((void**)&eo,   g_eo);
    cudaGetSymbolAddress((void**)&moS,  g_mo);
    cudaGetSymbolAddress((void**)&gates,g_gates);
    cudaGetSymbolAddress((void**)&w3,   g_w3);
    cudaGetSymbolAddress((void**)&w2p,  g_w2);

    // weight layout: w3: fc1 comps [0,1,2]*HH_, fc2 comps [3,4,5]*HH_
    // w2p: ew1 units at [0,12)*HH_, ew2 at [12,24)*HH_, tw1 at [24,30)*HH_
    bf16* fc1t = w3;
    bf16* fc2t = w3 + 3 * HH_;
    bf16* ew1t = w2p;
    bf16* ew2t = w2p + 12 * HH_;
    bf16* tw1t = w2p + 24 * HH_;

    const int SM2 = 2 * (2 * 2 * MB_);   // NSPL=2: 81920
    const int SM3 = 2 * (2 * 3 * MB_);   // NSPL=3: 122880
    cudaFuncSetAttribute((const void*)mma_gemm<3, true,  false, 3, false>,
                         cudaFuncAttributeMaxDynamicSharedMemorySize, SM3);
    cudaFuncSetAttribute((const void*)mma_gemm<3, false, true,  2, false>,
                         cudaFuncAttributeMaxDynamicSharedMemorySize, SM3);
    cudaFuncSetAttribute((const void*)mma_gemm<2, true,  false, 2, false>,
                         cudaFuncAttributeMaxDynamicSharedMemorySize, SM2);
    cudaFuncSetAttribute((const void*)mma_gemm<2, false, true,  0, false>,
                         cudaFuncAttributeMaxDynamicSharedMemorySize, SM2);
    cudaFuncSetAttribute((const void*)mma_gemm<2, false, false, 0, true>,
                         cudaFuncAttributeMaxDynamicSharedMemorySize, SM2);

    const dim3 blk(256);
    const dim3 tb(32, 8);

    // conversions
    cvt3_kernel<<<(unsigned)(NH_ / 256), blk>>>(cls, clsS, clsS + NH_, clsS + 2 * NH_, NH_);
    transpose_w<3><<<dim3(32, 32, 1), tb>>>(fc1w, fc1t, fc1t, fc1t, 0);
    transpose_w<3><<<dim3(32, 32, 1), tb>>>(fc2w, fc2t, fc2t, fc2t, 0);
    transpose_w<2><<<dim3(32, 32, NEXP), tb>>>(ew1, ew1t, ew1t, nullptr, 2 * HH_);
    transpose_w<2><<<dim3(32, 32, NEXP), tb>>>(ew2, ew2t, ew2t, nullptr, 2 * HH_);
    transpose_w<2><<<dim3(32, 32, NTASK), tb>>>(tw1, tw1t, tw1t, nullptr, 2 * HH_);

    const dim3 g1(HDIM / BN, NROWS / BM, 1);
    const dim3 gE(HDIM / BN, NROWS / BM, NEXP);
    const dim3 gT(HDIM / BN, NROWS / BM, NTASK);

    // fc1: 3-way split in/out, relu
    mma_gemm<3, true, false, 3, false><<<g1, blk, SM3>>>(
        clsS, clsS + NH_, clsS + 2 * NH_,
        fc1t, fc1t + HH_, fc1t + 2 * HH_, fc1b,
        nullptr, h1S, h1S + NH_, h1S + 2 * NH_, nullptr, nullptr,
        0, 0, 0, 0, 0);
    // fc2: 3-way split in, fp32 + 2-way out
    mma_gemm<3, false, true, 2, false><<<g1, blk, SM3>>>(
        h1S, h1S + NH_, h1S + 2 * NH_,
        fc2t, fc2t + HH_, fc2t + 2 * HH_, fc2b,
        hf, hS, hS + NH_, nullptr, nullptr, nullptr,
        0, 0, 0, 0, 0);

    gate_kernel<<<(NTASK * NROWS) / 8, blk>>>(hf, wgate, gates);

    // experts layer 1: relu, 2-way out
    mma_gemm<2, true, false, 2, false><<<gE, blk, SM2>>>(
        hS, hS + NH_, nullptr,
        ew1t, ew1t + HH_, nullptr, eb1,
        nullptr, ehS, ehS + (long)NEXP * NH_, nullptr, nullptr, nullptr,
        0, 2 * HH_, HDIM, NH_, 0);
    // experts layer 2: fp32 out
    mma_gemm<2, false, true, 0, false><<<gE, blk, SM2>>>(
        ehS, ehS + (long)NEXP * NH_, nullptr,
        ew2t, ew2t + HH_, nullptr, eb2,
        eo, nullptr, nullptr, nullptr, nullptr, nullptr,
        NH_, 2 * HH_, HDIM, NH_, 0);

    combine_kernel<<<(unsigned)(NH_ / 256), blk>>>(eo, gates, moS, moS + (long)NTASK * NH_);

    // towers: fused relu + tw2 reduction
    init_out_kernel<<<(NTASK * NROWS + 255) / 256, blk>>>(out, tb2);
    mma_gemm<2, false, false, 0, true><<<gT, blk, SM2>>>(
        moS, moS + (long)NTASK * NH_, nullptr,
        tw1t, tw1t + HH_, nullptr, tb1,
        nullptr, nullptr, nullptr, nullptr, tw2, out,
        NH_, 2 * HH_, HDIM, 0, HDIM);
}

// round 6
// speedup vs baseline: 2.9965x; 1.1199x over previous
#include <cuda_runtime.h>
#include <cuda_fp16.h>
#include <math.h>
#include <stdint.h>

#define NROWS 16384
#define HDIM  1024
#define NEXP  6
#define NTASK 3
#define TOPK  3

typedef __half fp16;
#define NH_ ((long)NROWS * HDIM)          // 16777216
#define HH_ ((long)HDIM * HDIM)           // 1048576

// =============================== Scratch ===================================
__device__ __align__(256) fp16  g_cls[2 * NH_];            // 64 MB (hi, lo)
__device__ __align__(256) fp16  g_h1 [2 * NH_];            // 64 MB
__device__ __align__(256) fp16  g_h  [2 * NH_];            // 64 MB
__device__ __align__(256) fp16  g_eh [2 * NEXP * NH_];     // 384 MB
__device__ __align__(256) float g_eo [NEXP * NH_];         // 384 MB
__device__ __align__(256) fp16  g_mo [2 * NTASK * NH_];    // 192 MB
__device__ __align__(256) float g_gates[(long)NTASK * NROWS * NEXP];
// all transposed weights, 17 units x 2 comps: fc1,fc2,ew1(6),ew2(6),tw1(3)
__device__ __align__(256) fp16  g_wt [34 * HH_];           // 68 MB

// =============================== PTX helpers ===============================
__device__ __forceinline__ uint32_t smem_u32(const void* p) {
    uint32_t a;
    asm("{ .reg .u64 t; cvta.to.shared.u64 t, %1; cvt.u32.u64 %0, t; }" : "=r"(a) : "l"(p));
    return a;
}
__device__ __forceinline__ void cp16(uint32_t s, const void* g) {
    asm volatile("cp.async.cg.shared.global [%0], [%1], 16;" :: "r"(s), "l"(g) : "memory");
}
#define CP_COMMIT() asm volatile("cp.async.commit_group;" ::: "memory")
#define CP_WAIT1()  asm volatile("cp.async.wait_group 1;" ::: "memory")
#define CP_WAIT0()  asm volatile("cp.async.wait_group 0;" ::: "memory")

__device__ __forceinline__ void ldsm4(uint32_t (&r)[4], uint32_t addr) {
    asm volatile("ldmatrix.sync.aligned.m8n8.x4.shared.b16 {%0,%1,%2,%3}, [%4];"
                 : "=r"(r[0]), "=r"(r[1]), "=r"(r[2]), "=r"(r[3]) : "r"(addr));
}
__device__ __forceinline__ void mma_fp16(float (&d)[4], const uint32_t (&a)[4],
                                         uint32_t b0, uint32_t b1) {
    asm volatile(
        "mma.sync.aligned.m16n8k16.row.col.f32.f16.f16.f32 "
        "{%0,%1,%2,%3}, {%4,%5,%6,%7}, {%8,%9}, {%0,%1,%2,%3};"
        : "+f"(d[0]), "+f"(d[1]), "+f"(d[2]), "+f"(d[3])
        : "r"(a[0]), "r"(a[1]), "r"(a[2]), "r"(a[3]), "r"(b0), "r"(b1));
}

// ============================ split-fp16 GEMM ==============================
// C = op( (Ah+Al) @ (Bh+Bl)^T + bias ), 3 mma terms (drop Al*Bl ~ 2^-22).
// A[M,K] row-major comps; B[N,K] row-major comps (pre-transposed weights).
// CTA tile 128x128, K-chunk 32, 8 warps (4m x 2n), warp tile 32x64.
#define BM 128
#define BN 128
#define BK 32
#define NKCH (HDIM / BK)          // 32
#define MB_  10240                // one 128x32 fp16 matrix, 80B row stride
#define ROWB 80
#define SM_BYTES (2 * 4 * MB_)    // 2 stages x 4 matrices = 81920

template <bool RELU, bool WSPL, bool TOWER>
__global__ void __launch_bounds__(256, 2)
mma_gemm(const fp16* __restrict__ A0, const fp16* __restrict__ A1,
         const fp16* __restrict__ B0, const fp16* __restrict__ B1,
         const float* __restrict__ bias,
         float* __restrict__ Cf, fp16* __restrict__ C0, fp16* __restrict__ C1,
         const float* __restrict__ w2, float* __restrict__ outT,
         long sA, long sB, long sBias, long sC, long sW2)
{
    extern __shared__ char smem[];
    const uint32_t smbase = smem_u32(smem);
    const int tid = threadIdx.x, wid = tid >> 5, lane = tid & 31;
    const int z = blockIdx.z;
    const long row0 = (long)blockIdx.y * BM;
    const int  n0   = blockIdx.x * BN;

    const fp16* Ag0 = A0 + z * sA + row0 * HDIM;
    const fp16* Ag1 = A1 + z * sA + row0 * HDIM;
    const fp16* Bg0 = B0 + z * sB + (long)n0 * HDIM;
    const fp16* Bg1 = B1 + z * sB + (long)n0 * HDIM;

    // stage loader: 512 (row,chunk) slots, 4 matrices (Ah, Al, Bh, Bl)
    auto ldstage = [&](int buf, int kc0) {
        const uint32_t sb = smbase + buf * (4 * MB_);
#pragma unroll
        for (int i = 0; i < 2; i++) {
            const int v = tid + 256 * i;
            const int r = v >> 2, ch = v & 3;
            const long g = (long)r * HDIM + kc0 + ch * 8;
            const uint32_t so = (uint32_t)(r * ROWB + ch * 16);
            cp16(sb + 0 * MB_ + so, Ag0 + g);
            cp16(sb + 1 * MB_ + so, Ag1 + g);
            cp16(sb + 2 * MB_ + so, Bg0 + g);
            cp16(sb + 3 * MB_ + so, Bg1 + g);
        }
    };

    float acc[2][8][4];
#pragma unroll
    for (int mt = 0; mt < 2; mt++)
#pragma unroll
        for (int nt = 0; nt < 8; nt++)
#pragma unroll
            for (int q = 0; q < 4; q++) acc[mt][nt][q] = 0.f;

    const int wm = (wid >> 1) * 32;
    const int wn = (wid & 1) * 64;
    const int grp = lane >> 3, lr = lane & 7;
    const int arow = lr + ((grp & 1) << 3);
    const int akb  = (grp >> 1) << 4;
    const int brow = lr + ((grp >> 1) << 3);
    const int bkb  = (grp & 1) << 4;

    ldstage(0, 0);
    CP_COMMIT();

    for (int c = 0; c < NKCH; c++) {
        if (c + 1 < NKCH) { ldstage((c + 1) & 1, (c + 1) * BK); CP_COMMIT(); CP_WAIT1(); }
        else              { CP_WAIT0(); }
        __syncthreads();

        const uint32_t sb = smbase + (c & 1) * (4 * MB_);
#pragma unroll
        for (int ks = 0; ks < 2; ks++) {
            uint32_t af[2][2][4];       // [comp][mt]
#pragma unroll
            for (int sc = 0; sc < 2; sc++)
#pragma unroll
                for (int mt = 0; mt < 2; mt++)
                    ldsm4(af[sc][mt],
                          sb + sc * MB_ + (wm + mt * 16 + arow) * ROWB + ks * 32 + akb);
#pragma unroll
            for (int np = 0; np < 4; np++) {
                uint32_t bfr[2][4];
#pragma unroll
                for (int sc = 0; sc < 2; sc++)
                    ldsm4(bfr[sc],
                          sb + (2 + sc) * MB_ + (wn + np * 16 + brow) * ROWB + ks * 32 + bkb);
#pragma unroll
                for (int mt = 0; mt < 2; mt++) {
                    // 3 terms: hh, hl, lh
                    mma_fp16(acc[mt][2 * np],     af[0][mt], bfr[0][0], bfr[0][1]);
                    mma_fp16(acc[mt][2 * np + 1], af[0][mt], bfr[0][2], bfr[0][3]);
                    mma_fp16(acc[mt][2 * np],     af[0][mt], bfr[1][0], bfr[1][1]);
                    mma_fp16(acc[mt][2 * np + 1], af[0][mt], bfr[1][2], bfr[1][3]);
                    mma_fp16(acc[mt][2 * np],     af[1][mt], bfr[0][0], bfr[0][1]);
                    mma_fp16(acc[mt][2 * np + 1], af[1][mt], bfr[0][2], bfr[0][3]);
                }
            }
        }
        __syncthreads();
    }

    // ------------------------------ epilogue ------------------------------
    const float* biasz = bias + z * sBias;
    const float* w2z   = TOWER ? (w2 + z * sW2) : nullptr;

#pragma unroll
    for (int mt = 0; mt < 2; mt++) {
#pragma unroll
        for (int half = 0; half < 2; half++) {
            const long gr = row0 + wm + mt * 16 + (lane >> 2) + half * 8;
            float p = 0.f;
#pragma unroll
            for (int nt = 0; nt < 8; nt++) {
                const int cc = n0 + wn + nt * 8 + (lane & 3) * 2;
                float v0 = acc[mt][nt][half * 2 + 0] + biasz[cc];
                float v1 = acc[mt][nt][half * 2 + 1] + biasz[cc + 1];
                if (RELU || TOWER) { v0 = fmaxf(v0, 0.f); v1 = fmaxf(v1, 0.f); }
                if (TOWER) {
                    p = fmaf(v0, w2z[cc], p);
                    p = fmaf(v1, w2z[cc + 1], p);
                } else {
                    const long off = z * sC + gr * HDIM + cc;
                    if (Cf != nullptr)
                        *reinterpret_cast<float2*>(&Cf[off]) = make_float2(v0, v1);
                    if (WSPL) {
                        fp16 h0 = __float2half_rn(v0), h1 = __float2half_rn(v1);
                        fp16 l0 = __float2half_rn(v0 - __half2float(h0));
                        fp16 l1 = __float2half_rn(v1 - __half2float(h1));
                        *reinterpret_cast<uint32_t*>(&C0[off]) =
                            (uint32_t)__half_as_ushort(h0) |
                            ((uint32_t)__half_as_ushort(h1) << 16);
                        *reinterpret_cast<uint32_t*>(&C1[off]) =
                            (uint32_t)__half_as_ushort(l0) |
                            ((uint32_t)__half_as_ushort(l1) << 16);
                    }
                }
            }
            if (TOWER) {
                p += __shfl_down_sync(0xffffffffu, p, 2);
                p += __shfl_down_sync(0xffffffffu, p, 1);
                if ((lane & 3) == 0)
                    atomicAdd(&outT[(long)z * NROWS + gr], p);
            }
        }
    }
}

// ======================= conversion / small kernels ========================
__global__ __launch_bounds__(256)
void cvt2_kernel(const float* __restrict__ in, fp16* __restrict__ c0,
                 fp16* __restrict__ c1, long n)
{
    const long i = (long)blockIdx.x * blockDim.x + threadIdx.x;
    if (i >= n) return;
    const float v = in[i];
    const fp16 h = __float2half_rn(v);
    c0[i] = h;
    c1[i] = __float2half_rn(v - __half2float(h));
}

// W[z][k][n] -> T comps [z][n][k]: comp0 at z*2HH_, comp1 at z*2HH_+HH_
__global__ __launch_bounds__(256)
void transpose_w(const float* __restrict__ W, fp16* __restrict__ T)
{
    __shared__ float tile[32][33];
    const int z = blockIdx.z;
    const float* Wz = W + (long)z * HH_;
    const long ob = (long)z * 2 * HH_;
    const int k0 = blockIdx.y * 32, n0 = blockIdx.x * 32;
    for (int i = threadIdx.y; i < 32; i += 8)
        tile[i][threadIdx.x] = Wz[(long)(k0 + i) * HDIM + n0 + threadIdx.x];
    __syncthreads();
    for (int i = threadIdx.y; i < 32; i += 8) {
        const float v = tile[threadIdx.x][i];
        const fp16 h = __float2half_rn(v);
        const long o = ob + (long)(n0 + i) * HDIM + k0 + threadIdx.x;
        T[o] = h;
        T[o + HH_] = __float2half_rn(v - __half2float(h));
    }
}

// Gating on split h (h = h0 + h1): one warp per (t,n).
__global__ __launch_bounds__(256)
void gate_kernel(const fp16* __restrict__ h0, const fp16* __restrict__ h1,
                 const float* __restrict__ wg, float* __restrict__ gates)
{
    const int warp = (blockIdx.x * blockDim.x + threadIdx.x) >> 5;
    const int lane = threadIdx.x & 31;
    if (warp >= NTASK * NROWS) return;
    const int t = warp / NROWS;
    const int n = warp - t * NROWS;

    float acc[NEXP];
#pragma unroll
    for (int e = 0; e < NEXP; e++) acc[e] = 0.f;
    const fp16* hr0 = h0 + (long)n * HDIM;
    const fp16* hr1 = h1 + (long)n * HDIM;
    const float* wt = wg + (long)t * HDIM * NEXP;
    for (int hh = lane; hh < HDIM; hh += 32) {
        const float hv = __half2float(hr0[hh]) + __half2float(hr1[hh]);
        const float* wr = wt + (long)hh * NEXP;
#pragma unroll
        for (int e = 0; e < NEXP; e++) acc[e] = fmaf(hv, wr[e], acc[e]);
    }
#pragma unroll
    for (int off = 16; off > 0; off >>= 1)
#pragma unroll
        for (int e = 0; e < NEXP; e++)
            acc[e] += __shfl_xor_sync(0xffffffffu, acc[e], off);

    if (lane == 0) {
        float v[NEXP];
#pragma unroll
        for (int e = 0; e < NEXP; e++) v[e] = acc[e];
        int ti[TOPK]; float tv[TOPK];
#pragma unroll
        for (int s = 0; s < TOPK; s++) {
            int bi = 0; float bv = v[0];
#pragma unroll
            for (int e = 1; e < NEXP; e++) if (v[e] > bv) { bv = v[e]; bi = e; }
            ti[s] = bi; tv[s] = bv; v[bi] = -INFINITY;
        }
        const float m = tv[0];
        float w[TOPK], s = 0.f;
#pragma unroll
        for (int k = 0; k < TOPK; k++) { w[k] = expf(tv[k] - m); s += w[k]; }
        const float inv = 1.f / s;
        float gv[NEXP];
#pragma unroll
        for (int e = 0; e < NEXP; e++) gv[e] = 0.f;
#pragma unroll
        for (int k = 0; k < TOPK; k++) gv[ti[k]] = w[k] * inv;
        float* gp = gates + ((long)t * NROWS + n) * NEXP;
#pragma unroll
        for (int e = 0; e < NEXP; e++) gp[e] = gv[e];
    }
}

__global__ __launch_bounds__(256)
void combine_kernel(const float* __restrict__ eo, const float* __restrict__ gates,
                    fp16* __restrict__ m0, fp16* __restrict__ m1)
{
    const long idx = (long)blockIdx.x * blockDim.x + threadIdx.x;
    if (idx >= NH_) return;
    const int n = (int)(idx >> 10);

    float v[NEXP];
#pragma unroll
    for (int e = 0; e < NEXP; e++) v[e] = eo[(long)e * NH_ + idx];

#pragma unroll
    for (int t = 0; t < NTASK; t++) {
        const float* gp = gates + ((long)t * NROWS + n) * NEXP;
        float r = 0.f;
#pragma unroll
        for (int e = 0; e < NEXP; e++) r = fmaf(gp[e], v[e], r);
        const fp16 h = __float2half_rn(r);
        m0[(long)t * NH_ + idx] = h;
        m1[(long)t * NH_ + idx] = __float2half_rn(r - __half2float(h));
    }
}

__global__ void init_out_kernel(float* __restrict__ out, const float* __restrict__ tb2)
{
    const int i = blockIdx.x * blockDim.x + threadIdx.x;
    if (i < NTASK * NROWS) out[i] = tb2[i / NROWS];
}

// ================================ launch ===================================
extern "C" void kernel_launch(void* const* d_in, const int* in_sizes, int n_in,
                              void* d_out, int out_size)
{
    const float* cls   = (const float*)d_in[0];
    const float* fc1w  = (const float*)d_in[1];
    const float* fc1b  = (const float*)d_in[2];
    const float* fc2w  = (const float*)d_in[3];
    const float* fc2b  = (const float*)d_in[4];
    const float* wgate = (const float*)d_in[5];
    const float* ew1   = (const float*)d_in[6];
    const float* eb1   = (const float*)d_in[7];
    const float* ew2   = (const float*)d_in[8];
    const float* eb2   = (const float*)d_in[9];
    const float* tw1   = (const float*)d_in[10];
    const float* tb1   = (const float*)d_in[11];
    const float* tw2   = (const float*)d_in[12];
    const float* tb2   = (const float*)d_in[13];
    float* out = (float*)d_out;

    fp16 *clsS, *h1S, *hS, *ehS, *moS, *wt;
    float *eo, *gates;
    cudaGetSymbolAddress((void**)&clsS, g_cls);
    cudaGetSymbolAddress((void**)&h1S,  g_h1);
    cudaGetSymbolAddress((void**)&hS,   g_h);
    cudaGetSymbolAddress((void**)&ehS,  g_eh);
    cudaGetSymbolAddress((void**)&eo,   g_eo);
    cudaGetSymbolAddress((void**)&moS,  g_mo);
    cudaGetSymbolAddress((void**)&gates,g_gates);
    cudaGetSymbolAddress((void**)&wt,   g_wt);

    // weight pool: unit u occupies [2u*HH_, 2u*HH_+2HH_): comp0, comp1
    fp16* fc1t = wt;                 // unit 0
    fp16* fc2t = wt + 2 * HH_;       // unit 1
    fp16* ew1t = wt + 4 * HH_;       // units 2..7
    fp16* ew2t = wt + 16 * HH_;      // units 8..13
    fp16* tw1t = wt + 28 * HH_;      // units 14..16

    cudaFuncSetAttribute((const void*)mma_gemm<true,  true,  false>,
                         cudaFuncAttributeMaxDynamicSharedMemorySize, SM_BYTES);
    cudaFuncSetAttribute((const void*)mma_gemm<false, true,  false>,
                         cudaFuncAttributeMaxDynamicSharedMemorySize, SM_BYTES);
    cudaFuncSetAttribute((const void*)mma_gemm<false, false, false>,
                         cudaFuncAttributeMaxDynamicSharedMemorySize, SM_BYTES);
    cudaFuncSetAttribute((const void*)mma_gemm<false, false, true>,
                         cudaFuncAttributeMaxDynamicSharedMemorySize, SM_BYTES);

    const dim3 blk(256);
    const dim3 tb(32, 8);
    const dim3 g1(HDIM / BN, NROWS / BM, 1);
    const dim3 gE(HDIM / BN, NROWS / BM, NEXP);
    const dim3 gT(HDIM / BN, NROWS / BM, NTASK);

    // launch order arranged so ncu -s 5 -c 1 profiles the fc1 GEMM (launch #5)
    transpose_w<<<dim3(32, 32, 1), tb>>>(fc1w, fc1t);            // 0
    transpose_w<<<dim3(32, 32, 1), tb>>>(fc2w, fc2t);            // 1
    transpose_w<<<dim3(32, 32, NEXP), tb>>>(ew1, ew1t);          // 2
    transpose_w<<<dim3(32, 32, NEXP), tb>>>(ew2, ew2t);          // 3
    cvt2_kernel<<<(unsigned)(NH_ / 256), blk>>>(cls, clsS, clsS + NH_, NH_);  // 4

    // 5: fc1 (relu, split out)
    mma_gemm<true, true, false><<<g1, blk, SM_BYTES>>>(
        clsS, clsS + NH_, fc1t, fc1t + HH_, fc1b,
        nullptr, h1S, h1S + NH_, nullptr, nullptr,
        0, 0, 0, 0, 0);
    // 6: fc2 (split out only; gate reads comps)
    mma_gemm<false, true, false><<<g1, blk, SM_BYTES>>>(
        h1S, h1S + NH_, fc2t, fc2t + HH_, fc2b,
        nullptr, hS, hS + NH_, nullptr, nullptr,
        0, 0, 0, 0, 0);

    transpose_w<<<dim3(32, 32, NTASK), tb>>>(tw1, tw1t);         // 7
    gate_kernel<<<(NTASK * NROWS) / 8, blk>>>(hS, hS + NH_, wgate, gates);  // 8

    // experts layer 1: relu, split out
    mma_gemm<true, true, false><<<gE, blk, SM_BYTES>>>(
        hS, hS + NH_, ew1t, ew1t + HH_, eb1,
        nullptr, ehS, ehS + (long)NEXP * NH_, nullptr, nullptr,
        0, 2 * HH_, HDIM, NH_, 0);
    // experts layer 2: fp32 out
    mma_gemm<false, false, false><<<gE, blk, SM_BYTES>>>(
        ehS, ehS + (long)NEXP * NH_, ew2t, ew2t + HH_, eb2,
        eo, nullptr, nullptr, nullptr, nullptr,
        NH_, 2 * HH_, HDIM, NH_, 0);

    combine_kernel<<<(unsigned)(NH_ / 256), blk>>>(eo, gates, moS, moS + (long)NTASK * NH_);

    // towers: fused relu + tw2 reduction
    init_out_kernel<<<(NTASK * NROWS + 255) / 256, blk>>>(out, tb2);
    mma_gemm<false, false, true><<<gT, blk, SM_BYTES>>>(
        moS, moS + (long)NTASK * NH_, tw1t, tw1t + HH_, tb1,
        nullptr, nullptr, nullptr, tw2, out,
        NH_, 2 * HH_, HDIM, 0, HDIM);
}

// round 7
// speedup vs baseline: 3.1770x; 1.0602x over previous
#include <cuda_runtime.h>
#include <cuda_fp16.h>
#include <math.h>
#include <stdint.h>

#define NROWS 16384
#define HDIM  1024
#define NEXP  6
#define NTASK 3
#define TOPK  3

typedef __half fp16;
#define NH_ ((long)NROWS * HDIM)          // 16777216
#define HH_ ((long)HDIM * HDIM)           // 1048576

// =============================== Scratch ===================================
__device__ __align__(256) fp16  g_cls[2 * NH_];
__device__ __align__(256) fp16  g_h1 [2 * NH_];
__device__ __align__(256) fp16  g_h  [2 * NH_];
__device__ __align__(256) fp16  g_eh [2 * NEXP * NH_];
__device__ __align__(256) float g_eo [NEXP * NH_];
__device__ __align__(256) fp16  g_mo [2 * NTASK * NH_];
__device__ __align__(256) float g_gates[(long)NTASK * NROWS * NEXP];
__device__ __align__(256) fp16  g_wt [34 * HH_];

// =============================== PTX helpers ===============================
__device__ __forceinline__ uint32_t smem_u32(const void* p) {
    uint32_t a;
    asm("{ .reg .u64 t; cvta.to.shared.u64 t, %1; cvt.u32.u64 %0, t; }" : "=r"(a) : "l"(p));
    return a;
}
__device__ __forceinline__ void cp16(uint32_t s, const void* g) {
    asm volatile("cp.async.cg.shared.global [%0], [%1], 16;" :: "r"(s), "l"(g) : "memory");
}
#define CP_COMMIT() asm volatile("cp.async.commit_group;" ::: "memory")
#define CP_WAIT1()  asm volatile("cp.async.wait_group 1;" ::: "memory")
#define CP_WAIT0()  asm volatile("cp.async.wait_group 0;" ::: "memory")

__device__ __forceinline__ void ldsm4(uint32_t (&r)[4], uint32_t addr) {
    asm volatile("ldmatrix.sync.aligned.m8n8.x4.shared.b16 {%0,%1,%2,%3}, [%4];"
                 : "=r"(r[0]), "=r"(r[1]), "=r"(r[2]), "=r"(r[3]) : "r"(addr));
}
__device__ __forceinline__ void mma_fp16(float (&d)[4], const uint32_t (&a)[4],
                                         uint32_t b0, uint32_t b1) {
    asm volatile(
        "mma.sync.aligned.m16n8k16.row.col.f32.f16.f16.f32 "
        "{%0,%1,%2,%3}, {%4,%5,%6,%7}, {%8,%9}, {%0,%1,%2,%3};"
        : "+f"(d[0]), "+f"(d[1]), "+f"(d[2]), "+f"(d[3])
        : "r"(a[0]), "r"(a[1]), "r"(a[2]), "r"(a[3]), "r"(b0), "r"(b1));
}

// ============================ split-fp16 GEMM ==============================
// C = op( (Ah+Al) @ (Bh+Bl)^T + bias ), 3 mma terms (drop Al*Bl ~ 2^-22).
// CTA tile 128x128, K-chunk 32, 4 warps (2m x 2n), warp tile 64x64.
#define BM 128
#define BN 128
#define BK 32
#define NKCH (HDIM / BK)          // 32
#define MB_  10240                // one 128x32 fp16 matrix, 80B row stride
#define ROWB 80
#define SM_BYTES (2 * 4 * MB_)    // 2 stages x 4 matrices = 81920
#define GEMM_THREADS 128

template <bool RELU, bool WSPL, bool TOWER>
__global__ void __launch_bounds__(GEMM_THREADS, 2)
mma_gemm(const fp16* __restrict__ A0, const fp16* __restrict__ A1,
         const fp16* __restrict__ B0, const fp16* __restrict__ B1,
         const float* __restrict__ bias,
         float* __restrict__ Cf, fp16* __restrict__ C0, fp16* __restrict__ C1,
         const float* __restrict__ w2, float* __restrict__ outT,
         long sA, long sB, long sBias, long sC, long sW2)
{
    extern __shared__ char smem[];
    const uint32_t smbase = smem_u32(smem);
    const int tid = threadIdx.x, wid = tid >> 5, lane = tid & 31;
    const int z = blockIdx.z;
    const long row0 = (long)blockIdx.y * BM;
    const int  n0   = blockIdx.x * BN;

    const fp16* Ag0 = A0 + z * sA + row0 * HDIM;
    const fp16* Ag1 = A1 + z * sA + row0 * HDIM;
    const fp16* Bg0 = B0 + z * sB + (long)n0 * HDIM;
    const fp16* Bg1 = B1 + z * sB + (long)n0 * HDIM;

    // stage loader: 4 matrices x 128 rows x 64B of k-chunk; 128 threads,
    // each thread does 4 rows per matrix slab (512 slots / 128).
    auto ldstage = [&](int buf, int kc0) {
        const uint32_t sb = smbase + buf * (4 * MB_);
#pragma unroll
        for (int i = 0; i < 4; i++) {
            const int v = tid + GEMM_THREADS * i;
            const int r = v >> 2, ch = v & 3;
            const long g = (long)r * HDIM + kc0 + ch * 8;
            const uint32_t so = (uint32_t)(r * ROWB + ch * 16);
            cp16(sb + 0 * MB_ + so, Ag0 + g);
            cp16(sb + 1 * MB_ + so, Ag1 + g);
            cp16(sb + 2 * MB_ + so, Bg0 + g);
            cp16(sb + 3 * MB_ + so, Bg1 + g);
        }
    };

    float acc[4][8][4];               // [m16 block][n8 block][quad] = 128 regs
#pragma unroll
    for (int mt = 0; mt < 4; mt++)
#pragma unroll
        for (int nt = 0; nt < 8; nt++)
#pragma unroll
            for (int q = 0; q < 4; q++) acc[mt][nt][q] = 0.f;

    const int wm = (wid & 1) * 64;    // warp m offset
    const int wn = (wid >> 1) * 64;   // warp n offset
    const int grp = lane >> 3, lr = lane & 7;
    const int arow = lr + ((grp & 1) << 3);
    const int akb  = (grp >> 1) << 4;
    const int brow = lr + ((grp >> 1) << 3);
    const int bkb  = (grp & 1) << 4;

    ldstage(0, 0);
    CP_COMMIT();

    for (int c = 0; c < NKCH; c++) {
        if (c + 1 < NKCH) { ldstage((c + 1) & 1, (c + 1) * BK); CP_COMMIT(); CP_WAIT1(); }
        else              { CP_WAIT0(); }
        __syncthreads();

        const uint32_t sb = smbase + (c & 1) * (4 * MB_);
#pragma unroll
        for (int ks = 0; ks < 2; ks++) {
            uint32_t af[2][4][4];     // [comp][mt]
            uint32_t bfr[2][4][4];    // [comp][np]
#pragma unroll
            for (int sc = 0; sc < 2; sc++)
#pragma unroll
                for (int mt = 0; mt < 4; mt++)
                    ldsm4(af[sc][mt],
                          sb + sc * MB_ + (wm + mt * 16 + arow) * ROWB + ks * 32 + akb);
#pragma unroll
            for (int sc = 0; sc < 2; sc++)
#pragma unroll
                for (int np = 0; np < 4; np++)
                    ldsm4(bfr[sc][np],
                          sb + (2 + sc) * MB_ + (wn + np * 16 + brow) * ROWB + ks * 32 + bkb);

            // term-major: 32 independent acc targets between same-acc mmas
#pragma unroll
            for (int term = 0; term < 3; term++) {
                const int ai = (term == 2) ? 1 : 0;   // hh, hl, lh
                const int bi = (term == 1) ? 1 : 0;
#pragma unroll
                for (int np = 0; np < 4; np++)
#pragma unroll
                    for (int mt = 0; mt < 4; mt++) {
                        mma_fp16(acc[mt][2 * np],     af[ai][mt],
                                 bfr[bi][np][0], bfr[bi][np][1]);
                        mma_fp16(acc[mt][2 * np + 1], af[ai][mt],
                                 bfr[bi][np][2], bfr[bi][np][3]);
                    }
            }
        }
        __syncthreads();
    }

    // ------------------------------ epilogue ------------------------------
    const float* biasz = bias + z * sBias;
    const float* w2z   = TOWER ? (w2 + z * sW2) : nullptr;

#pragma unroll
    for (int mt = 0; mt < 4; mt++) {
#pragma unroll
        for (int half = 0; half < 2; half++) {
            const long gr = row0 + wm + mt * 16 + (lane >> 2) + half * 8;
            float p = 0.f;
#pragma unroll
            for (int nt = 0; nt < 8; nt++) {
                const int cc = n0 + wn + nt * 8 + (lane & 3) * 2;
                float v0 = acc[mt][nt][half * 2 + 0] + biasz[cc];
                float v1 = acc[mt][nt][half * 2 + 1] + biasz[cc + 1];
                if (RELU || TOWER) { v0 = fmaxf(v0, 0.f); v1 = fmaxf(v1, 0.f); }
                if (TOWER) {
                    p = fmaf(v0, w2z[cc], p);
                    p = fmaf(v1, w2z[cc + 1], p);
                } else {
                    const long off = z * sC + gr * HDIM + cc;
                    if (Cf != nullptr)
                        *reinterpret_cast<float2*>(&Cf[off]) = make_float2(v0, v1);
                    if (WSPL) {
                        fp16 h0 = __float2half_rn(v0), h1 = __float2half_rn(v1);
                        fp16 l0 = __float2half_rn(v0 - __half2float(h0));
                        fp16 l1 = __float2half_rn(v1 - __half2float(h1));
                        *reinterpret_cast<uint32_t*>(&C0[off]) =
                            (uint32_t)__half_as_ushort(h0) |
                            ((uint32_t)__half_as_ushort(h1) << 16);
                        *reinterpret_cast<uint32_t*>(&C1[off]) =
                            (uint32_t)__half_as_ushort(l0) |
                            ((uint32_t)__half_as_ushort(l1) << 16);
                    }
                }
            }
            if (TOWER) {
                p += __shfl_down_sync(0xffffffffu, p, 2);
                p += __shfl_down_sync(0xffffffffu, p, 1);
                if ((lane & 3) == 0)
                    atomicAdd(&outT[(long)z * NROWS + gr], p);
            }
        }
    }
}

// ======================= conversion / small kernels ========================
__global__ __launch_bounds__(256)
void cvt2_kernel(const float* __restrict__ in, fp16* __restrict__ c0,
                 fp16* __restrict__ c1, long n)
{
    const long i = (long)blockIdx.x * blockDim.x + threadIdx.x;
    if (i >= n) return;
    const float v = in[i];
    const fp16 h = __float2half_rn(v);
    c0[i] = h;
    c1[i] = __float2half_rn(v - __half2float(h));
}

// W[z][k][n] -> T comps [z][n][k]: comp0 at z*2HH_, comp1 at z*2HH_+HH_
__global__ __launch_bounds__(256)
void transpose_w(const float* __restrict__ W, fp16* __restrict__ T)
{
    __shared__ float tile[32][33];
    const int z = blockIdx.z;
    const float* Wz = W + (long)z * HH_;
    const long ob = (long)z * 2 * HH_;
    const int k0 = blockIdx.y * 32, n0 = blockIdx.x * 32;
    for (int i = threadIdx.y; i < 32; i += 8)
        tile[i][threadIdx.x] = Wz[(long)(k0 + i) * HDIM + n0 + threadIdx.x];
    __syncthreads();
    for (int i = threadIdx.y; i < 32; i += 8) {
        const float v = tile[threadIdx.x][i];
        const fp16 h = __float2half_rn(v);
        const long o = ob + (long)(n0 + i) * HDIM + k0 + threadIdx.x;
        T[o] = h;
        T[o + HH_] = __float2half_rn(v - __half2float(h));
    }
}

// Gating on split h (h = h0 + h1): one warp per (t,n).
__global__ __launch_bounds__(256)
void gate_kernel(const fp16* __restrict__ h0, const fp16* __restrict__ h1,
                 const float* __restrict__ wg, float* __restrict__ gates)
{
    const int warp = (blockIdx.x * blockDim.x + threadIdx.x) >> 5;
    const int lane = threadIdx.x & 31;
    if (warp >= NTASK * NROWS) return;
    const int t = warp / NROWS;
    const int n = warp - t * NROWS;

    float acc[NEXP];
#pragma unroll
    for (int e = 0; e < NEXP; e++) acc[e] = 0.f;
    const fp16* hr0 = h0 + (long)n * HDIM;
    const fp16* hr1 = h1 + (long)n * HDIM;
    const float* wt = wg + (long)t * HDIM * NEXP;
    for (int hh = lane; hh < HDIM; hh += 32) {
        const float hv = __half2float(hr0[hh]) + __half2float(hr1[hh]);
        const float* wr = wt + (long)hh * NEXP;
#pragma unroll
        for (int e = 0; e < NEXP; e++) acc[e] = fmaf(hv, wr[e], acc[e]);
    }
#pragma unroll
    for (int off = 16; off > 0; off >>= 1)
#pragma unroll
        for (int e = 0; e < NEXP; e++)
            acc[e] += __shfl_xor_sync(0xffffffffu, acc[e], off);

    if (lane == 0) {
        float v[NEXP];
#pragma unroll
        for (int e = 0; e < NEXP; e++) v[e] = acc[e];
        int ti[TOPK]; float tv[TOPK];
#pragma unroll
        for (int s = 0; s < TOPK; s++) {
            int bi = 0; float bv = v[0];
#pragma unroll
            for (int e = 1; e < NEXP; e++) if (v[e] > bv) { bv = v[e]; bi = e; }
            ti[s] = bi; tv[s] = bv; v[bi] = -INFINITY;
        }
        const float m = tv[0];
        float w[TOPK], s = 0.f;
#pragma unroll
        for (int k = 0; k < TOPK; k++) { w[k] = expf(tv[k] - m); s += w[k]; }
        const float inv = 1.f / s;
        float gv[NEXP];
#pragma unroll
        for (int e = 0; e < NEXP; e++) gv[e] = 0.f;
#pragma unroll
        for (int k = 0; k < TOPK; k++) gv[ti[k]] = w[k] * inv;
        float* gp = gates + ((long)t * NROWS + n) * NEXP;
#pragma unroll
        for (int e = 0; e < NEXP; e++) gp[e] = gv[e];
    }
}

__global__ __launch_bounds__(256)
void combine_kernel(const float* __restrict__ eo, const float* __restrict__ gates,
                    fp16* __restrict__ m0, fp16* __restrict__ m1)
{
    const long idx = (long)blockIdx.x * blockDim.x + threadIdx.x;
    if (idx >= NH_) return;
    const int n = (int)(idx >> 10);

    float v[NEXP];
#pragma unroll
    for (int e = 0; e < NEXP; e++) v[e] = eo[(long)e * NH_ + idx];

#pragma unroll
    for (int t = 0; t < NTASK; t++) {
        const float* gp = gates + ((long)t * NROWS + n) * NEXP;
        float r = 0.f;
#pragma unroll
        for (int e = 0; e < NEXP; e++) r = fmaf(gp[e], v[e], r);
        const fp16 h = __float2half_rn(r);
        m0[(long)t * NH_ + idx] = h;
        m1[(long)t * NH_ + idx] = __float2half_rn(r - __half2float(h));
    }
}

__global__ void init_out_kernel(float* __restrict__ out, const float* __restrict__ tb2)
{
    const int i = blockIdx.x * blockDim.x + threadIdx.x;
    if (i < NTASK * NROWS) out[i] = tb2[i / NROWS];
}

// ================================ launch ===================================
extern "C" void kernel_launch(void* const* d_in, const int* in_sizes, int n_in,
                              void* d_out, int out_size)
{
    const float* cls   = (const float*)d_in[0];
    const float* fc1w  = (const float*)d_in[1];
    const float* fc1b  = (const float*)d_in[2];
    const float* fc2w  = (const float*)d_in[3];
    const float* fc2b  = (const float*)d_in[4];
    const float* wgate = (const float*)d_in[5];
    const float* ew1   = (const float*)d_in[6];
    const float* eb1   = (const float*)d_in[7];
    const float* ew2   = (const float*)d_in[8];
    const float* eb2   = (const float*)d_in[9];
    const float* tw1   = (const float*)d_in[10];
    const float* tb1   = (const float*)d_in[11];
    const float* tw2   = (const float*)d_in[12];
    const float* tb2   = (const float*)d_in[13];
    float* out = (float*)d_out;

    fp16 *clsS, *h1S, *hS, *ehS, *moS, *wt;
    float *eo, *gates;
    cudaGetSymbolAddress((void**)&clsS, g_cls);
    cudaGetSymbolAddress((void**)&h1S,  g_h1);
    cudaGetSymbolAddress((void**)&hS,   g_h);
    cudaGetSymbolAddress((void**)&ehS,  g_eh);
    cudaGetSymbolAddress((void**)&eo,   g_eo);
    cudaGetSymbolAddress((void**)&moS,  g_mo);
    cudaGetSymbolAddress((void**)&gates,g_gates);
    cudaGetSymbolAddress((void**)&wt,   g_wt);

    fp16* fc1t = wt;                 // unit 0
    fp16* fc2t = wt + 2 * HH_;       // unit 1
    fp16* ew1t = wt + 4 * HH_;       // units 2..7
    fp16* ew2t = wt + 16 * HH_;      // units 8..13
    fp16* tw1t = wt + 28 * HH_;      // units 14..16

    cudaFuncSetAttribute((const void*)mma_gemm<true,  true,  false>,
                         cudaFuncAttributeMaxDynamicSharedMemorySize, SM_BYTES);
    cudaFuncSetAttribute((const void*)mma_gemm<false, true,  false>,
                         cudaFuncAttributeMaxDynamicSharedMemorySize, SM_BYTES);
    cudaFuncSetAttribute((const void*)mma_gemm<false, false, false>,
                         cudaFuncAttributeMaxDynamicSharedMemorySize, SM_BYTES);
    cudaFuncSetAttribute((const void*)mma_gemm<false, false, true>,
                         cudaFuncAttributeMaxDynamicSharedMemorySize, SM_BYTES);

    const dim3 blk(256);
    const dim3 gblk(GEMM_THREADS);
    const dim3 tb(32, 8);
    const dim3 g1(HDIM / BN, NROWS / BM, 1);
    const dim3 gE(HDIM / BN, NROWS / BM, NEXP);
    const dim3 gT(HDIM / BN, NROWS / BM, NTASK);

    transpose_w<<<dim3(32, 32, 1), tb>>>(fc1w, fc1t);            // 0
    transpose_w<<<dim3(32, 32, 1), tb>>>(fc2w, fc2t);            // 1
    transpose_w<<<dim3(32, 32, NEXP), tb>>>(ew1, ew1t);          // 2
    transpose_w<<<dim3(32, 32, NEXP), tb>>>(ew2, ew2t);          // 3
    cvt2_kernel<<<(unsigned)(NH_ / 256), blk>>>(cls, clsS, clsS + NH_, NH_);  // 4

    // 5: fc1 (relu, split out)
    mma_gemm<true, true, false><<<g1, gblk, SM_BYTES>>>(
        clsS, clsS + NH_, fc1t, fc1t + HH_, fc1b,
        nullptr, h1S, h1S + NH_, nullptr, nullptr,
        0, 0, 0, 0, 0);
    // 6: fc2 (split out only; gate reads comps)
    mma_gemm<false, true, false><<<g1, gblk, SM_BYTES>>>(
        h1S, h1S + NH_, fc2t, fc2t + HH_, fc2b,
        nullptr, hS, hS + NH_, nullptr, nullptr,
        0, 0, 0, 0, 0);

    transpose_w<<<dim3(32, 32, NTASK), tb>>>(tw1, tw1t);         // 7
    gate_kernel<<<(NTASK * NROWS) / 8, blk>>>(hS, hS + NH_, wgate, gates);  // 8

    // experts layer 1: relu, split out
    mma_gemm<true, true, false><<<gE, gblk, SM_BYTES>>>(
        hS, hS + NH_, ew1t, ew1t + HH_, eb1,
        nullptr, ehS, ehS + (long)NEXP * NH_, nullptr, nullptr,
        0, 2 * HH_, HDIM, NH_, 0);
    // experts layer 2: fp32 out
    mma_gemm<false, false, false><<<gE, gblk, SM_BYTES>>>(
        ehS, ehS + (long)NEXP * NH_, ew2t, ew2t + HH_, eb2,
        eo, nullptr, nullptr, nullptr, nullptr,
        NH_, 2 * HH_, HDIM, NH_, 0);

    combine_kernel<<<(unsigned)(NH_ / 256), blk>>>(eo, gates, moS, moS + (long)NTASK * NH_);

    // towers: fused relu + tw2 reduction
    init_out_kernel<<<(NTASK * NROWS + 255) / 256, blk>>>(out, tb2);
    mma_gemm<false, false, true><<<gT, gblk, SM_BYTES>>>(
        moS, moS + (long)NTASK * NH_, tw1t, tw1t + HH_, tb1,
        nullptr, nullptr, nullptr, tw2, out,
        NH_, 2 * HH_, HDIM, 0, HDIM);
}

// round 8
// speedup vs baseline: 3.7120x; 1.1684x over previous
#include <cuda_runtime.h>
#include <cuda_fp16.h>
#include <math.h>
#include <stdint.h>

#define NROWS 16384
#define HDIM  1024
#define NEXP  6
#define NTASK 3
#define TOPK  3

typedef __half fp16;
#define NH_ ((long)NROWS * HDIM)          // 16777216
#define HH_ ((long)HDIM * HDIM)           // 1048576

// =============================== Scratch ===================================
__device__ __align__(256) fp16  g_cls[2 * NH_];
__device__ __align__(256) fp16  g_h1 [2 * NH_];
__device__ __align__(256) fp16  g_h  [2 * NH_];
__device__ __align__(256) fp16  g_eh [2 * NEXP * NH_];
__device__ __align__(256) float g_eo [NEXP * NH_];
__device__ __align__(256) fp16  g_mo [2 * NTASK * NH_];
__device__ __align__(256) float g_gates[(long)NTASK * NROWS * NEXP];
__device__ __align__(256) fp16  g_wt [34 * HH_];

// =============================== PTX helpers ===============================
__device__ __forceinline__ uint32_t smem_u32(const void* p) {
    uint32_t a;
    asm("{ .reg .u64 t; cvta.to.shared.u64 t, %1; cvt.u32.u64 %0, t; }" : "=r"(a) : "l"(p));
    return a;
}
__device__ __forceinline__ void cp16(uint32_t s, const void* g) {
    asm volatile("cp.async.cg.shared.global [%0], [%1], 16;" :: "r"(s), "l"(g) : "memory");
}
#define CP_COMMIT() asm volatile("cp.async.commit_group;" ::: "memory")
#define CP_WAIT1()  asm volatile("cp.async.wait_group 1;" ::: "memory")
#define CP_WAIT0()  asm volatile("cp.async.wait_group 0;" ::: "memory")

__device__ __forceinline__ void ldsm4(uint32_t (&r)[4], uint32_t addr) {
    asm volatile("ldmatrix.sync.aligned.m8n8.x4.shared.b16 {%0,%1,%2,%3}, [%4];"
                 : "=r"(r[0]), "=r"(r[1]), "=r"(r[2]), "=r"(r[3]) : "r"(addr));
}
__device__ __forceinline__ void mma_fp16(float (&d)[4], const uint32_t (&a)[4],
                                         uint32_t b0, uint32_t b1) {
    asm volatile(
        "mma.sync.aligned.m16n8k16.row.col.f32.f16.f16.f32 "
        "{%0,%1,%2,%3}, {%4,%5,%6,%7}, {%8,%9}, {%0,%1,%2,%3};"
        : "+f"(d[0]), "+f"(d[1]), "+f"(d[2]), "+f"(d[3])
        : "r"(a[0]), "r"(a[1]), "r"(a[2]), "r"(a[3]), "r"(b0), "r"(b1));
}

// ============================ split-fp16 GEMM ==============================
// C = op( (Ah+Al) @ (Bh+Bl)^T + bias ), 3 mma terms (drop Al*Bl ~ 2^-22).
// CTA tile 128x128, K-chunk 32, 4 warps (2m x 2n), warp tile 64x64.
// SMEM: 64B rows with XOR swizzle (c16 ^= (row>>1)&3) — conflict-free for
// cp.async 16B stores and ldmatrix (group = (4r + c16^((r>>1)&3)) mod 8 is a
// permutation over each 8-lane phase). 3-stage cp.async pipeline, ONE
// __syncthreads per chunk: {WAIT1; sync; compute c; load c+2}.
#define BM 128
#define BN 128
#define BK 32
#define NKCH (HDIM / BK)          // 32
#define MB_  8192                 // one 128x32 fp16 matrix, 64B rows
#define STG  (4 * MB_)            // 32768 per stage
#define SM_BYTES (3 * STG)        // 98304
#define GEMM_THREADS 128

__device__ __forceinline__ uint32_t swz(int row, int c16) {
    return (uint32_t)(row * 64 + ((c16 ^ ((row >> 1) & 3)) << 4));
}

template <bool RELU, bool WSPL, bool TOWER>
__global__ void __launch_bounds__(GEMM_THREADS, 2)
mma_gemm(const fp16* __restrict__ A0, const fp16* __restrict__ A1,
         const fp16* __restrict__ B0, const fp16* __restrict__ B1,
         const float* __restrict__ bias,
         float* __restrict__ Cf, fp16* __restrict__ C0, fp16* __restrict__ C1,
         const float* __restrict__ w2, float* __restrict__ outT,
         long sA, long sB, long sBias, long sC, long sW2)
{
    extern __shared__ char smem[];
    const uint32_t smbase = smem_u32(smem);
    const int tid = threadIdx.x, wid = tid >> 5, lane = tid & 31;
    const int z = blockIdx.z;
    const long row0 = (long)blockIdx.y * BM;
    const int  n0   = blockIdx.x * BN;

    const fp16* Ag0 = A0 + z * sA + row0 * HDIM;
    const fp16* Ag1 = A1 + z * sA + row0 * HDIM;
    const fp16* Bg0 = B0 + z * sB + (long)n0 * HDIM;
    const fp16* Bg1 = B1 + z * sB + (long)n0 * HDIM;

    // loader: thread v -> row r = v>>2, 16B col ch = v&3; 4 iters x 4 matrices
    const int ldr0 = tid >> 2, ldch = tid & 3;
    auto ldstage = [&](int buf, int kc0) {
        const uint32_t sb = smbase + buf * STG;
#pragma unroll
        for (int i = 0; i < 4; i++) {
            const int r = ldr0 + 32 * i;
            const long g = (long)r * HDIM + kc0 + ldch * 8;
            const uint32_t so = swz(r, ldch);
            cp16(sb + 0 * MB_ + so, Ag0 + g);
            cp16(sb + 1 * MB_ + so, Ag1 + g);
            cp16(sb + 2 * MB_ + so, Bg0 + g);
            cp16(sb + 3 * MB_ + so, Bg1 + g);
        }
    };

    float acc[4][8][4];               // 128 regs
#pragma unroll
    for (int mt = 0; mt < 4; mt++)
#pragma unroll
        for (int nt = 0; nt < 8; nt++)
#pragma unroll
            for (int q = 0; q < 4; q++) acc[mt][nt][q] = 0.f;

    const int wm = (wid & 1) * 64;
    const int wn = (wid >> 1) * 64;
    const int grp = lane >> 3, lr = lane & 7;
    const int arow = lr + ((grp & 1) << 3);
    const int ac16 = grp >> 1;            // 16B col within ks half
    const int brow = lr + ((grp >> 1) << 3);
    const int bc16 = grp & 1;

    // per-thread ldsm bases (row fixed per mt/np)
    uint32_t abase[4], axm[4], bbase[4], bxm[4];
#pragma unroll
    for (int mt = 0; mt < 4; mt++) {
        const int r = wm + mt * 16 + arow;
        abase[mt] = (uint32_t)(r * 64);
        axm[mt]   = (uint32_t)((r >> 1) & 3);
    }
#pragma unroll
    for (int np = 0; np < 4; np++) {
        const int r = wn + np * 16 + brow;
        bbase[np] = (uint32_t)(r * 64);
        bxm[np]   = (uint32_t)((r >> 1) & 3);
    }

    ldstage(0, 0);           CP_COMMIT();
    ldstage(1, BK);          CP_COMMIT();

    for (int c = 0; c < NKCH; c++) {
        if (c + 1 < NKCH) CP_WAIT1(); else CP_WAIT0();
        __syncthreads();     // chunk c published; buffer (c+2)%3 free

        const uint32_t sb = smbase + (c % 3) * STG;
#pragma unroll
        for (int ks = 0; ks < 2; ks++) {
            uint32_t af[2][4][4];
            uint32_t bfr[2][4][4];
            const uint32_t ka = (uint32_t)(ks * 2 + ac16);
            const uint32_t kb = (uint32_t)(ks * 2 + bc16);
#pragma unroll
            for (int sc = 0; sc < 2; sc++)
#pragma unroll
                for (int mt = 0; mt < 4; mt++)
                    ldsm4(af[sc][mt],
                          sb + sc * MB_ + abase[mt] + ((ka ^ axm[mt]) << 4));
#pragma unroll
            for (int sc = 0; sc < 2; sc++)
#pragma unroll
                for (int np = 0; np < 4; np++)
                    ldsm4(bfr[sc][np],
                          sb + (2 + sc) * MB_ + bbase[np] + ((kb ^ bxm[np]) << 4));

#pragma unroll
            for (int term = 0; term < 3; term++) {
                const int ai = (term == 2) ? 1 : 0;   // hh, hl, lh
                const int bi = (term == 1) ? 1 : 0;
#pragma unroll
                for (int np = 0; np < 4; np++)
#pragma unroll
                    for (int mt = 0; mt < 4; mt++) {
                        mma_fp16(acc[mt][2 * np],     af[ai][mt],
                                 bfr[bi][np][0], bfr[bi][np][1]);
                        mma_fp16(acc[mt][2 * np + 1], af[ai][mt],
                                 bfr[bi][np][2], bfr[bi][np][3]);
                    }
            }
        }

        if (c + 2 < NKCH) { ldstage((c + 2) % 3, (c + 2) * BK); CP_COMMIT(); }
    }

    // ------------------------------ epilogue ------------------------------
    const float* biasz = bias + z * sBias;
    const float* w2z   = TOWER ? (w2 + z * sW2) : nullptr;

#pragma unroll
    for (int mt = 0; mt < 4; mt++) {
#pragma unroll
        for (int half = 0; half < 2; half++) {
            const long gr = row0 + wm + mt * 16 + (lane >> 2) + half * 8;
            float p = 0.f;
#pragma unroll
            for (int nt = 0; nt < 8; nt++) {
                const int cc = n0 + wn + nt * 8 + (lane & 3) * 2;
                float v0 = acc[mt][nt][half * 2 + 0] + biasz[cc];
                float v1 = acc[mt][nt][half * 2 + 1] + biasz[cc + 1];
                if (RELU || TOWER) { v0 = fmaxf(v0, 0.f); v1 = fmaxf(v1, 0.f); }
                if (TOWER) {
                    p = fmaf(v0, w2z[cc], p);
                    p = fmaf(v1, w2z[cc + 1], p);
                } else {
                    const long off = z * sC + gr * HDIM + cc;
                    if (Cf != nullptr)
                        *reinterpret_cast<float2*>(&Cf[off]) = make_float2(v0, v1);
                    if (WSPL) {
                        fp16 h0 = __float2half_rn(v0), h1 = __float2half_rn(v1);
                        fp16 l0 = __float2half_rn(v0 - __half2float(h0));
                        fp16 l1 = __float2half_rn(v1 - __half2float(h1));
                        *reinterpret_cast<uint32_t*>(&C0[off]) =
                            (uint32_t)__half_as_ushort(h0) |
                            ((uint32_t)__half_as_ushort(h1) << 16);
                        *reinterpret_cast<uint32_t*>(&C1[off]) =
                            (uint32_t)__half_as_ushort(l0) |
                            ((uint32_t)__half_as_ushort(l1) << 16);
                    }
                }
            }
            if (TOWER) {
                p += __shfl_down_sync(0xffffffffu, p, 2);
                p += __shfl_down_sync(0xffffffffu, p, 1);
                if ((lane & 3) == 0)
                    atomicAdd(&outT[(long)z * NROWS + gr], p);
            }
        }
    }
}

// ======================= conversion / small kernels ========================
__global__ __launch_bounds__(256)
void cvt2_kernel(const float* __restrict__ in, fp16* __restrict__ c0,
                 fp16* __restrict__ c1, long n)
{
    const long i = (long)blockIdx.x * blockDim.x + threadIdx.x;
    if (i >= n) return;
    const float v = in[i];
    const fp16 h = __float2half_rn(v);
    c0[i] = h;
    c1[i] = __float2half_rn(v - __half2float(h));
}

__global__ __launch_bounds__(256)
void transpose_w(const float* __restrict__ W, fp16* __restrict__ T)
{
    __shared__ float tile[32][33];
    const int z = blockIdx.z;
    const float* Wz = W + (long)z * HH_;
    const long ob = (long)z * 2 * HH_;
    const int k0 = blockIdx.y * 32, n0 = blockIdx.x * 32;
    for (int i = threadIdx.y; i < 32; i += 8)
        tile[i][threadIdx.x] = Wz[(long)(k0 + i) * HDIM + n0 + threadIdx.x];
    __syncthreads();
    for (int i = threadIdx.y; i < 32; i += 8) {
        const float v = tile[threadIdx.x][i];
        const fp16 h = __float2half_rn(v);
        const long o = ob + (long)(n0 + i) * HDIM + k0 + threadIdx.x;
        T[o] = h;
        T[o + HH_] = __float2half_rn(v - __half2float(h));
    }
}

__global__ __launch_bounds__(256)
void gate_kernel(const fp16* __restrict__ h0, const fp16* __restrict__ h1,
                 const float* __restrict__ wg, float* __restrict__ gates)
{
    const int warp = (blockIdx.x * blockDim.x + threadIdx.x) >> 5;
    const int lane = threadIdx.x & 31;
    if (warp >= NTASK * NROWS) return;
    const int t = warp / NROWS;
    const int n = warp - t * NROWS;

    float acc[NEXP];
#pragma unroll
    for (int e = 0; e < NEXP; e++) acc[e] = 0.f;
    const fp16* hr0 = h0 + (long)n * HDIM;
    const fp16* hr1 = h1 + (long)n * HDIM;
    const float* wt = wg + (long)t * HDIM * NEXP;
    for (int hh = lane; hh < HDIM; hh += 32) {
        const float hv = __half2float(hr0[hh]) + __half2float(hr1[hh]);
        const float* wr = wt + (long)hh * NEXP;
#pragma unroll
        for (int e = 0; e < NEXP; e++) acc[e] = fmaf(hv, wr[e], acc[e]);
    }
#pragma unroll
    for (int off = 16; off > 0; off >>= 1)
#pragma unroll
        for (int e = 0; e < NEXP; e++)
            acc[e] += __shfl_xor_sync(0xffffffffu, acc[e], off);

    if (lane == 0) {
        float v[NEXP];
#pragma unroll
        for (int e = 0; e < NEXP; e++) v[e] = acc[e];
        int ti[TOPK]; float tv[TOPK];
#pragma unroll
        for (int s = 0; s < TOPK; s++) {
            int bi = 0; float bv = v[0];
#pragma unroll
            for (int e = 1; e < NEXP; e++) if (v[e] > bv) { bv = v[e]; bi = e; }
            ti[s] = bi; tv[s] = bv; v[bi] = -INFINITY;
        }
        const float m = tv[0];
        float w[TOPK], s = 0.f;
#pragma unroll
        for (int k = 0; k < TOPK; k++) { w[k] = expf(tv[k] - m); s += w[k]; }
        const float inv = 1.f / s;
        float gv[NEXP];
#pragma unroll
        for (int e = 0; e < NEXP; e++) gv[e] = 0.f;
#pragma unroll
        for (int k = 0; k < TOPK; k++) gv[ti[k]] = w[k] * inv;
        float* gp = gates + ((long)t * NROWS + n) * NEXP;
#pragma unroll
        for (int e = 0; e < NEXP; e++) gp[e] = gv[e];
    }
}

__global__ __launch_bounds__(256)
void combine_kernel(const float* __restrict__ eo, const float* __restrict__ gates,
                    fp16* __restrict__ m0, fp16* __restrict__ m1)
{
    const long idx = (long)blockIdx.x * blockDim.x + threadIdx.x;
    if (idx >= NH_) return;
    const int n = (int)(idx >> 10);

    float v[NEXP];
#pragma unroll
    for (int e = 0; e < NEXP; e++) v[e] = eo[(long)e * NH_ + idx];

#pragma unroll
    for (int t = 0; t < NTASK; t++) {
        const float* gp = gates + ((long)t * NROWS + n) * NEXP;
        float r = 0.f;
#pragma unroll
        for (int e = 0; e < NEXP; e++) r = fmaf(gp[e], v[e], r);
        const fp16 h = __float2half_rn(r);
        m0[(long)t * NH_ + idx] = h;
        m1[(long)t * NH_ + idx] = __float2half_rn(r - __half2float(h));
    }
}

__global__ void init_out_kernel(float* __restrict__ out, const float* __restrict__ tb2)
{
    const int i = blockIdx.x * blockDim.x + threadIdx.x;
    if (i < NTASK * NROWS) out[i] = tb2[i / NROWS];
}

// ================================ launch ===================================
extern "C" void kernel_launch(void* const* d_in, const int* in_sizes, int n_in,
                              void* d_out, int out_size)
{
    const float* cls   = (const float*)d_in[0];
    const float* fc1w  = (const float*)d_in[1];
    const float* fc1b  = (const float*)d_in[2];
    const float* fc2w  = (const float*)d_in[3];
    const float* fc2b  = (const float*)d_in[4];
    const float* wgate = (const float*)d_in[5];
    const float* ew1   = (const float*)d_in[6];
    const float* eb1   = (const float*)d_in[7];
    const float* ew2   = (const float*)d_in[8];
    const float* eb2   = (const float*)d_in[9];
    const float* tw1   = (const float*)d_in[10];
    const float* tb1   = (const float*)d_in[11];
    const float* tw2   = (const float*)d_in[12];
    const float* tb2   = (const float*)d_in[13];
    float* out = (float*)d_out;

    fp16 *clsS, *h1S, *hS, *ehS, *moS, *wt;
    float *eo, *gates;
    cudaGetSymbolAddress((void**)&clsS, g_cls);
    cudaGetSymbolAddress((void**)&h1S,  g_h1);
    cudaGetSymbolAddress((void**)&hS,   g_h);
    cudaGetSymbolAddress((void**)&ehS,  g_eh);
    cudaGetSymbolAddress((void**)&eo,   g_eo);
    cudaGetSymbolAddress((void**)&moS,  g_mo);
    cudaGetSymbolAddress((void**)&gates,g_gates);
    cudaGetSymbolAddress((void**)&wt,   g_wt);

    fp16* fc1t = wt;                 // unit 0
    fp16* fc2t = wt + 2 * HH_;       // unit 1
    fp16* ew1t = wt + 4 * HH_;       // units 2..7
    fp16* ew2t = wt + 16 * HH_;      // units 8..13
    fp16* tw1t = wt + 28 * HH_;      // units 14..16

    cudaFuncSetAttribute((const void*)mma_gemm<true,  true,  false>,
                         cudaFuncAttributeMaxDynamicSharedMemorySize, SM_BYTES);
    cudaFuncSetAttribute((const void*)mma_gemm<false, true,  false>,
                         cudaFuncAttributeMaxDynamicSharedMemorySize, SM_BYTES);
    cudaFuncSetAttribute((const void*)mma_gemm<false, false, false>,
                         cudaFuncAttributeMaxDynamicSharedMemorySize, SM_BYTES);
    cudaFuncSetAttribute((const void*)mma_gemm<false, false, true>,
                         cudaFuncAttributeMaxDynamicSharedMemorySize, SM_BYTES);

    const dim3 blk(256);
    const dim3 gblk(GEMM_THREADS);
    const dim3 tb(32, 8);
    const dim3 g1(HDIM / BN, NROWS / BM, 1);
    const dim3 gE(HDIM / BN, NROWS / BM, NEXP);
    const dim3 gT(HDIM / BN, NROWS / BM, NTASK);

    // prologue conversions first; GEMMs land at launch idx 6-7 for ncu
    transpose_w<<<dim3(32, 32, 1), tb>>>(fc1w, fc1t);            // 0
    transpose_w<<<dim3(32, 32, 1), tb>>>(fc2w, fc2t);            // 1
    transpose_w<<<dim3(32, 32, NEXP), tb>>>(ew1, ew1t);          // 2
    transpose_w<<<dim3(32, 32, NEXP), tb>>>(ew2, ew2t);          // 3
    transpose_w<<<dim3(32, 32, NTASK), tb>>>(tw1, tw1t);         // 4
    cvt2_kernel<<<(unsigned)(NH_ / 256), blk>>>(cls, clsS, clsS + NH_, NH_);  // 5

    // 6: fc1 (relu, split out)
    mma_gemm<true, true, false><<<g1, gblk, SM_BYTES>>>(
        clsS, clsS + NH_, fc1t, fc1t + HH_, fc1b,
        nullptr, h1S, h1S + NH_, nullptr, nullptr,
        0, 0, 0, 0, 0);
    // 7: fc2 (split out only; gate reads comps)
    mma_gemm<false, true, false><<<g1, gblk, SM_BYTES>>>(
        h1S, h1S + NH_, fc2t, fc2t + HH_, fc2b,
        nullptr, hS, hS + NH_, nullptr, nullptr,
        0, 0, 0, 0, 0);

    gate_kernel<<<(NTASK * NROWS) / 8, blk>>>(hS, hS + NH_, wgate, gates);  // 8

    // experts layer 1: relu, split out
    mma_gemm<true, true, false><<<gE, gblk, SM_BYTES>>>(
        hS, hS + NH_, ew1t, ew1t + HH_, eb1,
        nullptr, ehS, ehS + (long)NEXP * NH_, nullptr, nullptr,
        0, 2 * HH_, HDIM, NH_, 0);
    // experts layer 2: fp32 out
    mma_gemm<false, false, false><<<gE, gblk, SM_BYTES>>>(
        ehS, ehS + (long)NEXP * NH_, ew2t, ew2t + HH_, eb2,
        eo, nullptr, nullptr, nullptr, nullptr,
        NH_, 2 * HH_, HDIM, NH_, 0);

    combine_kernel<<<(unsigned)(NH_ / 256), blk>>>(eo, gates, moS, moS + (long)NTASK * NH_);

    // towers: fused relu + tw2 reduction
    init_out_kernel<<<(NTASK * NROWS + 255) / 256, blk>>>(out, tb2);
    mma_gemm<false, false, true><<<gT, gblk, SM_BYTES>>>(
        moS, moS + (long)NTASK * NH_, tw1t, tw1t + HH_, tb1,
        nullptr, nullptr, nullptr, tw2, out,
        NH_, 2 * HH_, HDIM, 0, HDIM);
}